// round 1
// baseline (speedup 1.0000x reference)
#include <cuda_runtime.h>
#include <math.h>

#define BSZ   8
#define C1    256
#define C2    256
#define CM    128
#define Hh    80
#define Ww    80
#define HW    6400
#define N9    9
#define KCN   1152      // CM * 9
#define NOFF  27
#define EPSF  1e-5f

// ---------------- scratch (device globals; no runtime alloc) ----------------
__device__ __align__(16) float g_y   [BSZ*HW*CM];     // NHWC  y = silu(bn1(conv1))
__device__ __align__(16) float g_pred[BSZ*HW*NOFF];   // per-pixel [27]: 18 raw off + 9 sigmoid mask
__device__ __align__(16) float g_z   [BSZ*HW*CM];     // NHWC  deform+bn2+silu
__device__ __align__(16) float g_w1t [C1*CM];         // [k=256][o=128]
__device__ __align__(16) float g_wdt [KCN*CM];        // [k=c*9+n][o=128]
__device__ __align__(16) float g_w3t [CM*C2];         // [k=128][o=256]
__device__ __align__(16) float g_w2r [KCN*28];        // [(c*9+n)][oc pad 28]

__device__ __forceinline__ float silu_f(float v){ return v / (1.f + __expf(-v)); }

// ---------------- K0: weight transposes ----------------
__global__ void prep_kernel(const float* __restrict__ w1, const float* __restrict__ w2,
                            const float* __restrict__ wd, const float* __restrict__ w3){
    int i = blockIdx.x*blockDim.x + threadIdx.x;
    if (i < C1*CM){ int k=i/CM, o=i%CM; g_w1t[i] = w1[o*C1 + k]; }
    if (i < KCN*CM){ int k=i/CM, o=i%CM; g_wdt[i] = wd[o*KCN + k]; }
    if (i < CM*C2){ int k=i/C2, o=i%C2; g_w3t[i] = w3[o*CM + k]; }
    if (i < KCN*28){ int k=i/28, oc=i%28; g_w2r[i] = (oc<NOFF) ? w2[oc*KCN + k] : 0.f; }
}

// ---------------- K1: conv1x1(256->128) + bn1 + silu -> g_y (NHWC) ----------------
// GEMM M=51200 px, K=256, N=128. Block: 64px x 128o, 128 threads, 8x8 thread tile.
__global__ void __launch_bounds__(128) k1_conv1(const float* __restrict__ x,
        const float* __restrict__ g1, const float* __restrict__ b1,
        const float* __restrict__ m1, const float* __restrict__ v1){
    __shared__ float Xs[16][64];
    __shared__ float Ws[16][128];
    int blk = blockIdx.x;
    int b_ = blk / 100;
    int p0 = (blk % 100) * 64;
    const float* xb = x + (size_t)b_ * C1 * HW;
    int tid = threadIdx.x, tx = tid & 15, ty = tid >> 4;
    float acc[8][8] = {};
    for (int k0 = 0; k0 < C1; k0 += 16){
        #pragma unroll
        for (int i = 0; i < 8; i++){
            int idx = tid + i*128; int kk = idx >> 6, pp = idx & 63;
            Xs[kk][pp] = xb[(k0+kk)*HW + p0 + pp];
        }
        #pragma unroll
        for (int i = 0; i < 16; i++){
            int idx = tid + i*128; int kk = idx >> 7, o = idx & 127;
            Ws[kk][o] = g_w1t[(k0+kk)*CM + o];
        }
        __syncthreads();
        #pragma unroll
        for (int kk = 0; kk < 16; kk++){
            float a[8], bb[8];
            #pragma unroll
            for (int i = 0; i < 8; i++) a[i] = Xs[kk][ty*8 + i];
            #pragma unroll
            for (int j = 0; j < 8; j++) bb[j] = Ws[kk][tx*8 + j];
            #pragma unroll
            for (int i = 0; i < 8; i++)
                #pragma unroll
                for (int j = 0; j < 8; j++) acc[i][j] += a[i]*bb[j];
        }
        __syncthreads();
    }
    #pragma unroll
    for (int j = 0; j < 8; j++){
        int o = tx*8 + j;
        float s = g1[o] * rsqrtf(v1[o] + EPSF);
        float t = b1[o] - m1[o]*s;
        #pragma unroll
        for (int i = 0; i < 8; i++){
            float vv = acc[i][j]*s + t;
            g_y[(size_t)(b_*HW + p0 + ty*8 + i)*CM + o] = silu_f(vv);
        }
    }
}

// ---------------- K2: conv3x3(128->27) on g_y; raw offsets + sigmoid mask -> g_pred ----------------
// Block = (b, 16x16 spatial tile), 256 threads, 1 pixel/thread, acc[27].
__global__ void __launch_bounds__(256) k2_offsets(const float* __restrict__ offb){
    __shared__ float ys[16*324];      // [cc][18*18]
    __shared__ float ws[16*9*28];     // [cc][n][oc(28)]
    int b_ = blockIdx.x / 25;
    int tile = blockIdx.x % 25;
    int th0 = (tile/5)*16, tw0 = (tile%5)*16;
    int tid = threadIdx.x, lx = tid & 15, ly = tid >> 4;
    float acc[27] = {};
    for (int c0 = 0; c0 < CM; c0 += 16){
        for (int s = tid; s < 324; s += 256){
            int sy = s/18 - 1 + th0, sx = s%18 - 1 + tw0;
            bool ok = (sy>=0 && sy<Hh && sx>=0 && sx<Ww);
            const float* src = &g_y[(size_t)(b_*HW + sy*Ww + sx)*CM + c0];
            #pragma unroll
            for (int cc = 0; cc < 16; cc++)
                ys[cc*324 + s] = ok ? src[cc] : 0.f;
        }
        for (int s = tid; s < 16*9*28; s += 256) ws[s] = g_w2r[c0*9*28 + s];
        __syncthreads();
        #pragma unroll 2
        for (int cc = 0; cc < 16; cc++){
            float yv[9];
            #pragma unroll
            for (int n = 0; n < 9; n++)
                yv[n] = ys[cc*324 + (ly + n/3)*18 + (lx + n%3)];
            #pragma unroll
            for (int n = 0; n < 9; n++){
                const float* wp = &ws[(cc*9 + n)*28];
                #pragma unroll
                for (int oc = 0; oc < 27; oc++) acc[oc] += yv[n]*wp[oc];
            }
        }
        __syncthreads();
    }
    size_t base = (size_t)(b_*HW + (th0+ly)*Ww + (tw0+lx)) * NOFF;
    #pragma unroll
    for (int ch = 0; ch < 27; ch++){
        float vv = acc[ch] + offb[ch];
        if (ch >= 18) vv = 1.f/(1.f + __expf(-vv));
        g_pred[base + ch] = vv;
    }
}

// ---------------- K3: deform conv (gather + implicit GEMM) + bn2 + silu -> g_z (NHWC) ----------------
// Block = 64 pixels, 256 threads. smem: samp[64][288] + coords[576] + Ws[8][128].
__global__ void __launch_bounds__(256) k3_deform(const float* __restrict__ dcnb,
        const float* __restrict__ g2, const float* __restrict__ b2,
        const float* __restrict__ m2, const float* __restrict__ v2){
    extern __shared__ float sm[];
    float* samp = sm;                         // 64*288 = 18432 floats
    float* wts  = sm + 18432;                 // 576*4
    int*   idxs = (int*)(sm + 18432 + 2304);  // 576*4
    float* Ws   = sm + 18432 + 2304 + 2304;   // 8*128
    int blk = blockIdx.x;
    int b_ = blk / 100;
    int p0 = (blk % 100) * 64;
    int tid = threadIdx.x;

    // Phase A0: per (pixel,tap) bilinear corner indices + mask/validity-folded weights
    for (int pr = tid; pr < 576; pr += 256){
        int p = pr / 9, n = pr % 9;
        int pg = p0 + p, h = pg / Ww, w = pg % Ww;
        size_t pb = (size_t)(b_*HW + pg) * NOFF;
        float oy = g_pred[pb + 2*n], ox = g_pred[pb + 2*n + 1], mk = g_pred[pb + 18 + n];
        float py = (float)(h - 1 + n/3) + oy;
        float px = (float)(w - 1 + n%3) + ox;
        float y0f = floorf(py), x0f = floorf(px);
        float wy = py - y0f, wx = px - x0f;
        int iy0 = (int)y0f, ix0 = (int)x0f, iy1 = iy0+1, ix1 = ix0+1;
        float vy0 = (iy0>=0 && iy0<Hh) ? 1.f : 0.f;
        float vy1 = (iy1>=0 && iy1<Hh) ? 1.f : 0.f;
        float vx0 = (ix0>=0 && ix0<Ww) ? 1.f : 0.f;
        float vx1 = (ix1>=0 && ix1<Ww) ? 1.f : 0.f;
        int cy0 = min(max(iy0,0),Hh-1), cy1 = min(max(iy1,0),Hh-1);
        int cx0 = min(max(ix0,0),Ww-1), cx1 = min(max(ix1,0),Ww-1);
        int base = b_*HW;
        idxs[pr*4+0] = (base + cy0*Ww + cx0)*CM;
        idxs[pr*4+1] = (base + cy0*Ww + cx1)*CM;
        idxs[pr*4+2] = (base + cy1*Ww + cx0)*CM;
        idxs[pr*4+3] = (base + cy1*Ww + cx1)*CM;
        wts[pr*4+0] = (1.f-wy)*(1.f-wx)*mk*vy0*vx0;
        wts[pr*4+1] = (1.f-wy)*wx      *mk*vy0*vx1;
        wts[pr*4+2] = wy*(1.f-wx)      *mk*vy1*vx0;
        wts[pr*4+3] = wy*wx            *mk*vy1*vx1;
    }

    float acc[4][8] = {};
    int tx = tid & 15, ty = tid >> 4;
    int px0 = ty*4, o0 = tx*8;
    int warp = tid >> 5, lane = tid & 31;

    for (int c0 = 0; c0 < CM; c0 += 32){
        __syncthreads();
        // gather: warp per (pixel,tap) pair, lane = channel within chunk
        for (int i = 0; i < 72; i++){
            int pr = warp*72 + i;
            int4   id = ((const int4*)  idxs)[pr];
            float4 wt = ((const float4*)wts )[pr];
            int c = c0 + lane;
            float v = wt.x*g_y[id.x + c] + wt.y*g_y[id.y + c]
                    + wt.z*g_y[id.z + c] + wt.w*g_y[id.w + c];
            int p = pr/9, n = pr%9;
            samp[p*288 + lane*9 + n] = v;   // stride 9 -> conflict-free
        }
        __syncthreads();
        for (int st = 0; st < 36; st++){
            {   // stage one 8x128 slab of Wd
                int kk = tid >> 5;
                ((float4*)Ws)[kk*32 + lane] =
                    ((const float4*)&g_wdt[(c0*9 + st*8 + kk)*CM])[lane];
            }
            __syncthreads();
            #pragma unroll
            for (int kk = 0; kk < 8; kk++){
                int k = st*8 + kk;
                float a[4], bb[8];
                #pragma unroll
                for (int i = 0; i < 4; i++) a[i] = samp[(px0+i)*288 + k];
                #pragma unroll
                for (int j = 0; j < 8; j++) bb[j] = Ws[kk*128 + o0 + j];
                #pragma unroll
                for (int i = 0; i < 4; i++)
                    #pragma unroll
                    for (int j = 0; j < 8; j++) acc[i][j] += a[i]*bb[j];
            }
            __syncthreads();
        }
    }
    #pragma unroll
    for (int j = 0; j < 8; j++){
        int o = o0 + j;
        float s = g2[o] * rsqrtf(v2[o] + EPSF);
        float t = b2[o] - m2[o]*s;
        #pragma unroll
        for (int i = 0; i < 4; i++){
            float vv = (acc[i][j] + dcnb[o])*s + t;
            g_z[(size_t)(b_*HW + p0 + px0 + i)*CM + o] = silu_f(vv);
        }
    }
}

// ---------------- K4: conv1x1(128->256) + bn3 + silu + residual -> out (NCHW) ----------------
__global__ void __launch_bounds__(128) k4_conv3(const float* __restrict__ x, float* __restrict__ out,
        const float* __restrict__ g3, const float* __restrict__ b3,
        const float* __restrict__ m3, const float* __restrict__ v3){
    __shared__ float Zs[16][65];
    __shared__ float Ws[16][128];
    int blk = blockIdx.x;
    int b_ = blk / 100;
    int p0 = (blk % 100) * 64;
    int o0g = blockIdx.y * 128;
    int tid = threadIdx.x, tx = tid & 15, ty = tid >> 4;
    float acc[8][8] = {};
    for (int k0 = 0; k0 < CM; k0 += 16){
        #pragma unroll
        for (int i = 0; i < 8; i++){
            int idx = tid + i*128; int pp = idx >> 4, kk = idx & 15;
            Zs[kk][pp] = g_z[(size_t)(b_*HW + p0 + pp)*CM + k0 + kk];
        }
        #pragma unroll
        for (int i = 0; i < 16; i++){
            int idx = tid + i*128; int kk = idx >> 7, o = idx & 127;
            Ws[kk][o] = g_w3t[(k0+kk)*C2 + o0g + o];
        }
        __syncthreads();
        #pragma unroll
        for (int kk = 0; kk < 16; kk++){
            float a[8], bb[8];
            #pragma unroll
            for (int i = 0; i < 8; i++) a[i] = Zs[kk][ty*8 + i];
            #pragma unroll
            for (int j = 0; j < 8; j++) bb[j] = Ws[kk][tx*8 + j];
            #pragma unroll
            for (int i = 0; i < 8; i++)
                #pragma unroll
                for (int j = 0; j < 8; j++) acc[i][j] += a[i]*bb[j];
        }
        __syncthreads();
    }
    #pragma unroll
    for (int j = 0; j < 8; j++){
        int o = o0g + tx*8 + j;
        float s = g3[o] * rsqrtf(v3[o] + EPSF);
        float t = b3[o] - m3[o]*s;
        #pragma unroll
        for (int i = 0; i < 8; i++){
            int pg = p0 + ty*8 + i;
            size_t oi = ((size_t)b_*C2 + o)*HW + pg;
            out[oi] = x[oi] + silu_f(acc[i][j]*s + t);
        }
    }
}

// ---------------- launch ----------------
extern "C" void kernel_launch(void* const* d_in, const int* in_sizes, int n_in,
                              void* d_out, int out_size){
    const float* x     = (const float*)d_in[0];
    const float* cv1_w = (const float*)d_in[1];
    const float* bn1g  = (const float*)d_in[2];
    const float* bn1b  = (const float*)d_in[3];
    const float* bn1m  = (const float*)d_in[4];
    const float* bn1v  = (const float*)d_in[5];
    const float* off_w = (const float*)d_in[6];
    const float* off_b = (const float*)d_in[7];
    const float* dcn_w = (const float*)d_in[8];
    const float* dcn_b = (const float*)d_in[9];
    const float* bn2g  = (const float*)d_in[10];
    const float* bn2b  = (const float*)d_in[11];
    const float* bn2m  = (const float*)d_in[12];
    const float* bn2v  = (const float*)d_in[13];
    const float* cv3_w = (const float*)d_in[14];
    const float* bn3g  = (const float*)d_in[15];
    const float* bn3b  = (const float*)d_in[16];
    const float* bn3m  = (const float*)d_in[17];
    const float* bn3v  = (const float*)d_in[18];
    float* out = (float*)d_out;

    prep_kernel<<<(KCN*CM + 255)/256, 256>>>(cv1_w, off_w, dcn_w, cv3_w);
    k1_conv1<<<BSZ*100, 128>>>(x, bn1g, bn1b, bn1m, bn1v);
    k2_offsets<<<BSZ*25, 256>>>(off_b);

    static int smem_set = 0;  // idempotent attribute set (same value every call)
    int smem_bytes = (18432 + 2304 + 2304 + 1024) * 4;  // 96256 B
    (void)smem_set;
    cudaFuncSetAttribute(k3_deform, cudaFuncAttributeMaxDynamicSharedMemorySize, smem_bytes);
    k3_deform<<<BSZ*100, 256, smem_bytes>>>(dcn_b, bn2g, bn2b, bn2m, bn2v);

    k4_conv3<<<dim3(BSZ*100, 2), 128>>>(x, out, bn3g, bn3b, bn3m, bn3v);
}

// round 3
// speedup vs baseline: 1.3402x; 1.3402x over previous
#include <cuda_runtime.h>
#include <math.h>
#include <stdint.h>

#define BSZ   8
#define C1    256
#define C2    256
#define CM    128
#define Hh    80
#define Ww    80
#define HW    6400
#define N9    9
#define KCN   1152      // CM * 9
#define NOFF  27
#define EPSF  1e-5f

// ---------------- scratch (device globals; no runtime alloc) ----------------
__device__ __align__(16) float g_y   [BSZ*HW*CM];     // NHWC  y = silu(bn1(conv1))
__device__ __align__(16) float g_pred[BSZ*HW*NOFF];   // per-pixel [27]
__device__ __align__(16) float g_z   [BSZ*HW*CM];     // NHWC  deform+bn2+silu
__device__ __align__(16) float g_w1t [C1*CM];         // [k=256][o=128]
__device__ __align__(16) float g_w3t [CM*C2];         // [k=128][o=256]
__device__ __align__(16) float g_w2r [KCN*28];        // [(c*9+n)][oc pad 28]
__device__ __align__(16) float g_wd2 [N9*CM*CM];      // [n][o][c]

__device__ __forceinline__ float silu_f(float v){ return v / (1.f + __expf(-v)); }

__device__ __forceinline__ uint32_t f2tf32(float v){
    uint32_t t; asm("cvt.rna.tf32.f32 %0, %1;" : "=r"(t) : "f"(v));
    return t;
}

// ---------------- K0: weight transposes ----------------
__global__ void prep_kernel(const float* __restrict__ w1, const float* __restrict__ w2,
                            const float* __restrict__ wd, const float* __restrict__ w3){
    int i = blockIdx.x*blockDim.x + threadIdx.x;
    if (i < C1*CM){ int k=i/CM, o=i%CM; g_w1t[i] = w1[o*C1 + k]; }
    if (i < CM*C2){ int k=i/C2, o=i%C2; g_w3t[i] = w3[o*CM + k]; }
    if (i < KCN*28){ int k=i/28, oc=i%28; g_w2r[i] = (oc<NOFF) ? w2[oc*KCN + k] : 0.f; }
    if (i < N9*CM*CM){
        int n = i/(CM*CM); int rest = i%(CM*CM); int o = rest/CM, c = rest%CM;
        g_wd2[i] = wd[o*KCN + c*9 + n];
    }
}

// ---------------- K1: conv1x1(256->128) + bn1 + silu -> g_y (NHWC) ----------------
__global__ void __launch_bounds__(128) k1_conv1(const float* __restrict__ x,
        const float* __restrict__ g1, const float* __restrict__ b1,
        const float* __restrict__ m1, const float* __restrict__ v1){
    __shared__ float Xs[16][64];
    __shared__ float Ws[16][128];
    int blk = blockIdx.x;
    int b_ = blk / 100;
    int p0 = (blk % 100) * 64;
    const float* xb = x + (size_t)b_ * C1 * HW;
    int tid = threadIdx.x, tx = tid & 15, ty = tid >> 4;
    float acc[8][8] = {};
    for (int k0 = 0; k0 < C1; k0 += 16){
        #pragma unroll
        for (int i = 0; i < 8; i++){
            int idx = tid + i*128; int kk = idx >> 6, pp = idx & 63;
            Xs[kk][pp] = xb[(k0+kk)*HW + p0 + pp];
        }
        #pragma unroll
        for (int i = 0; i < 16; i++){
            int idx = tid + i*128; int kk = idx >> 7, o = idx & 127;
            Ws[kk][o] = g_w1t[(k0+kk)*CM + o];
        }
        __syncthreads();
        #pragma unroll
        for (int kk = 0; kk < 16; kk++){
            float a[8], bb[8];
            #pragma unroll
            for (int i = 0; i < 8; i++) a[i] = Xs[kk][ty*8 + i];
            #pragma unroll
            for (int j = 0; j < 8; j++) bb[j] = Ws[kk][tx*8 + j];
            #pragma unroll
            for (int i = 0; i < 8; i++)
                #pragma unroll
                for (int j = 0; j < 8; j++) acc[i][j] += a[i]*bb[j];
        }
        __syncthreads();
    }
    #pragma unroll
    for (int j = 0; j < 8; j++){
        int o = tx*8 + j;
        float s = g1[o] * rsqrtf(v1[o] + EPSF);
        float t = b1[o] - m1[o]*s;
        #pragma unroll
        for (int i = 0; i < 8; i++){
            float vv = acc[i][j]*s + t;
            g_y[(size_t)(b_*HW + p0 + ty*8 + i)*CM + o] = silu_f(vv);
        }
    }
}

// ---------------- K2: conv3x3(128->27) on g_y -> g_pred ----------------
__global__ void __launch_bounds__(256) k2_offsets(const float* __restrict__ offb){
    __shared__ float ys[16*324];
    __shared__ float ws[16*9*28];
    int b_ = blockIdx.x / 25;
    int tile = blockIdx.x % 25;
    int th0 = (tile/5)*16, tw0 = (tile%5)*16;
    int tid = threadIdx.x, lx = tid & 15, ly = tid >> 4;
    float acc[27] = {};
    for (int c0 = 0; c0 < CM; c0 += 16){
        for (int s = tid; s < 324; s += 256){
            int sy = s/18 - 1 + th0, sx = s%18 - 1 + tw0;
            bool ok = (sy>=0 && sy<Hh && sx>=0 && sx<Ww);
            const float* src = &g_y[(size_t)(b_*HW + sy*Ww + sx)*CM + c0];
            #pragma unroll
            for (int cc = 0; cc < 16; cc++)
                ys[cc*324 + s] = ok ? src[cc] : 0.f;
        }
        for (int s = tid; s < 16*9*28; s += 256) ws[s] = g_w2r[c0*9*28 + s];
        __syncthreads();
        #pragma unroll 2
        for (int cc = 0; cc < 16; cc++){
            float yv[9];
            #pragma unroll
            for (int n = 0; n < 9; n++)
                yv[n] = ys[cc*324 + (ly + n/3)*18 + (lx + n%3)];
            #pragma unroll
            for (int n = 0; n < 9; n++){
                const float* wp = &ws[(cc*9 + n)*28];
                #pragma unroll
                for (int oc = 0; oc < 27; oc++) acc[oc] += yv[n]*wp[oc];
            }
        }
        __syncthreads();
    }
    size_t base = (size_t)(b_*HW + (th0+ly)*Ww + (tw0+lx)) * NOFF;
    #pragma unroll
    for (int ch = 0; ch < 27; ch++){
        float vv = acc[ch] + offb[ch];
        if (ch >= 18) vv = 1.f/(1.f + __expf(-vv));
        g_pred[base + ch] = vv;
    }
}

// ---------------- K3: deform conv via mma.sync tf32 -> g_z (NHWC) ----------------
// Block = 128 px x 128 o, 256 threads (8 warps; warp grid 4m x 2n, warp tile 32px x 64o).
// K = 1152 in 36 chunks of 32 (tap n = it/4, channel block = (it%4)*32).
#define APAD 36
// dynamic smem floats: As 128*36, Bs 128*36, sPy 1152, sPx 1152, sMk 1152, sS 128, sT 128
#define K3_F_AS   0
#define K3_F_BS   (128*APAD)
#define K3_F_PY   (2*128*APAD)
#define K3_F_PX   (K3_F_PY + 1152)
#define K3_F_MK   (K3_F_PX + 1152)
#define K3_F_S    (K3_F_MK + 1152)
#define K3_F_T    (K3_F_S + 128)
#define K3_SMEM_F (K3_F_T + 128)

__global__ void __launch_bounds__(256, 2) k3_deform_mma(const float* __restrict__ dcnb,
        const float* __restrict__ g2, const float* __restrict__ b2,
        const float* __restrict__ m2, const float* __restrict__ v2){
    extern __shared__ float sm[];
    uint32_t* As = (uint32_t*)(sm + K3_F_AS);
    uint32_t* Bs = (uint32_t*)(sm + K3_F_BS);
    float* sPy = sm + K3_F_PY;
    float* sPx = sm + K3_F_PX;
    float* sMk = sm + K3_F_MK;
    float* sS  = sm + K3_F_S;
    float* sT  = sm + K3_F_T;

    int blk = blockIdx.x;
    int b_ = blk / 50;
    int p0 = (blk % 50) * 128;
    int tid = threadIdx.x, warp = tid >> 5, lane = tid & 31;

    // setup: sample coords + bn params
    for (int pr = tid; pr < 128*9; pr += 256){
        int p = pr / 9, nn = pr % 9;
        int pg = p0 + p, h = pg / Ww, w = pg % Ww;
        size_t pb = (size_t)(b_*HW + pg) * NOFF;
        sPy[pr] = (float)(h - 1 + nn/3) + g_pred[pb + 2*nn];
        sPx[pr] = (float)(w - 1 + nn%3) + g_pred[pb + 2*nn + 1];
        sMk[pr] = g_pred[pb + 18 + nn];
    }
    if (tid < 128){
        float s = g2[tid] * rsqrtf(v2[tid] + EPSF);
        sS[tid] = s;
        sT[tid] = dcnb[tid]*s + b2[tid] - m2[tid]*s;
    }
    __syncthreads();

    int wm = warp & 3, wnn = warp >> 2;       // warp tile: rows wm*32.., cols wnn*64..
    int gid = lane >> 2, tig = lane & 3;
    float acc[2][8][4];
    #pragma unroll
    for (int mt = 0; mt < 2; mt++)
        #pragma unroll
        for (int nt = 0; nt < 8; nt++)
            #pragma unroll
            for (int q = 0; q < 4; q++) acc[mt][nt][q] = 0.f;

    const float* ybB = g_y + (size_t)(b_*HW)*CM;

    for (int it = 0; it < 36; it++){
        int n  = it >> 2;
        int c0 = (it & 3) << 5;

        // fill Bs[o][k] (tf32), coalesced: lane -> k
        const float* wn = g_wd2 + n*(CM*CM) + c0;
        #pragma unroll
        for (int i = 0; i < 16; i++){
            int e = i*256 + tid;
            int o = e >> 5, k = e & 31;
            Bs[o*APAD + k] = f2tf32(wn[o*CM + k]);
        }
        // fill As[px][k]: warp-per-16px, lane = channel; 4-corner bilinear gather
        const float* yb = ybB + c0 + lane;
        #pragma unroll 2
        for (int r = 0; r < 16; r++){
            int px = warp*16 + r;
            float py = sPy[px*9 + n], qx = sPx[px*9 + n], mk = sMk[px*9 + n];
            float y0f = floorf(py), x0f = floorf(qx);
            float wy = py - y0f, wx = qx - x0f;
            int iy0 = (int)y0f, ix0 = (int)x0f, iy1 = iy0 + 1, ix1 = ix0 + 1;
            float vy0 = (iy0 >= 0 && iy0 < Hh) ? 1.f : 0.f;
            float vy1 = (iy1 >= 0 && iy1 < Hh) ? 1.f : 0.f;
            float vx0 = (ix0 >= 0 && ix0 < Ww) ? 1.f : 0.f;
            float vx1 = (ix1 >= 0 && ix1 < Ww) ? 1.f : 0.f;
            int cy0 = min(max(iy0,0),Hh-1), cy1 = min(max(iy1,0),Hh-1);
            int cx0 = min(max(ix0,0),Ww-1), cx1 = min(max(ix1,0),Ww-1);
            float w00 = (1.f-wy)*(1.f-wx)*mk*vy0*vx0;
            float w01 = (1.f-wy)*wx      *mk*vy0*vx1;
            float w10 = wy*(1.f-wx)      *mk*vy1*vx0;
            float w11 = wy*wx            *mk*vy1*vx1;
            int i00 = (cy0*Ww + cx0)*CM, i01 = (cy0*Ww + cx1)*CM;
            int i10 = (cy1*Ww + cx0)*CM, i11 = (cy1*Ww + cx1)*CM;
            float v = w00*yb[i00] + w01*yb[i01] + w10*yb[i10] + w11*yb[i11];
            As[px*APAD + lane] = f2tf32(v);
        }
        __syncthreads();

        // mma: per warp 2m x 8n x 4k steps of m16n8k8
        const uint32_t* Ab = As + (wm*32 + gid)*APAD;
        const uint32_t* Bb = Bs + (wnn*64 + gid)*APAD;
        #pragma unroll
        for (int kk = 0; kk < 4; kk++){
            int kb = kk*8 + tig;
            uint32_t a[2][4];
            #pragma unroll
            for (int mt = 0; mt < 2; mt++){
                a[mt][0] = Ab[(mt*16)*APAD + kb];
                a[mt][1] = Ab[(mt*16+8)*APAD + kb];
                a[mt][2] = Ab[(mt*16)*APAD + kb + 4];
                a[mt][3] = Ab[(mt*16+8)*APAD + kb + 4];
            }
            #pragma unroll
            for (int nt = 0; nt < 8; nt++){
                uint32_t b0 = Bb[(nt*8)*APAD + kb];
                uint32_t b1 = Bb[(nt*8)*APAD + kb + 4];
                #pragma unroll
                for (int mt = 0; mt < 2; mt++){
                    asm volatile(
                        "mma.sync.aligned.m16n8k8.row.col.f32.tf32.tf32.f32 "
                        "{%0,%1,%2,%3}, {%4,%5,%6,%7}, {%8,%9}, {%0,%1,%2,%3};"
                        : "+f"(acc[mt][nt][0]), "+f"(acc[mt][nt][1]),
                          "+f"(acc[mt][nt][2]), "+f"(acc[mt][nt][3])
                        : "r"(a[mt][0]), "r"(a[mt][1]), "r"(a[mt][2]), "r"(a[mt][3]),
                          "r"(b0), "r"(b1));
                }
            }
        }
        __syncthreads();
    }

    // epilogue: bn2 + silu, NHWC float2 stores
    #pragma unroll
    for (int mt = 0; mt < 2; mt++){
        int r0 = wm*32 + mt*16 + gid;
        float* z0 = g_z + (size_t)(b_*HW + p0 + r0)*CM;
        float* z1 = g_z + (size_t)(b_*HW + p0 + r0 + 8)*CM;
        #pragma unroll
        for (int nt = 0; nt < 8; nt++){
            int cb = wnn*64 + nt*8 + 2*tig;
            float s0 = sS[cb], s1 = sS[cb+1], t0 = sT[cb], t1 = sT[cb+1];
            float2 v0, v1;
            v0.x = silu_f(acc[mt][nt][0]*s0 + t0);
            v0.y = silu_f(acc[mt][nt][1]*s1 + t1);
            v1.x = silu_f(acc[mt][nt][2]*s0 + t0);
            v1.y = silu_f(acc[mt][nt][3]*s1 + t1);
            *(float2*)(z0 + cb) = v0;
            *(float2*)(z1 + cb) = v1;
        }
    }
}

// ---------------- K4: conv1x1(128->256) + bn3 + silu + residual -> out (NCHW) ----------------
__global__ void __launch_bounds__(128) k4_conv3(const float* __restrict__ x, float* __restrict__ out,
        const float* __restrict__ g3, const float* __restrict__ b3,
        const float* __restrict__ m3, const float* __restrict__ v3){
    __shared__ float Zs[16][65];
    __shared__ float Ws[16][128];
    int blk = blockIdx.x;
    int b_ = blk / 100;
    int p0 = (blk % 100) * 64;
    int o0g = blockIdx.y * 128;
    int tid = threadIdx.x, tx = tid & 15, ty = tid >> 4;
    float acc[8][8] = {};
    for (int k0 = 0; k0 < CM; k0 += 16){
        #pragma unroll
        for (int i = 0; i < 8; i++){
            int idx = tid + i*128; int pp = idx >> 4, kk = idx & 15;
            Zs[kk][pp] = g_z[(size_t)(b_*HW + p0 + pp)*CM + k0 + kk];
        }
        #pragma unroll
        for (int i = 0; i < 16; i++){
            int idx = tid + i*128; int kk = idx >> 7, o = idx & 127;
            Ws[kk][o] = g_w3t[(k0+kk)*C2 + o0g + o];
        }
        __syncthreads();
        #pragma unroll
        for (int kk = 0; kk < 16; kk++){
            float a[8], bb[8];
            #pragma unroll
            for (int i = 0; i < 8; i++) a[i] = Zs[kk][ty*8 + i];
            #pragma unroll
            for (int j = 0; j < 8; j++) bb[j] = Ws[kk][tx*8 + j];
            #pragma unroll
            for (int i = 0; i < 8; i++)
                #pragma unroll
                for (int j = 0; j < 8; j++) acc[i][j] += a[i]*bb[j];
        }
        __syncthreads();
    }
    #pragma unroll
    for (int j = 0; j < 8; j++){
        int o = o0g + tx*8 + j;
        float s = g3[o] * rsqrtf(v3[o] + EPSF);
        float t = b3[o] - m3[o]*s;
        #pragma unroll
        for (int i = 0; i < 8; i++){
            int pg = p0 + ty*8 + i;
            size_t oi = ((size_t)b_*C2 + o)*HW + pg;
            out[oi] = x[oi] + silu_f(acc[i][j]*s + t);
        }
    }
}

// ---------------- launch ----------------
extern "C" void kernel_launch(void* const* d_in, const int* in_sizes, int n_in,
                              void* d_out, int out_size){
    const float* x     = (const float*)d_in[0];
    const float* cv1_w = (const float*)d_in[1];
    const float* bn1g  = (const float*)d_in[2];
    const float* bn1b  = (const float*)d_in[3];
    const float* bn1m  = (const float*)d_in[4];
    const float* bn1v  = (const float*)d_in[5];
    const float* off_w = (const float*)d_in[6];
    const float* off_b = (const float*)d_in[7];
    const float* dcn_w = (const float*)d_in[8];
    const float* dcn_b = (const float*)d_in[9];
    const float* bn2g  = (const float*)d_in[10];
    const float* bn2b  = (const float*)d_in[11];
    const float* bn2m  = (const float*)d_in[12];
    const float* bn2v  = (const float*)d_in[13];
    const float* cv3_w = (const float*)d_in[14];
    const float* bn3g  = (const float*)d_in[15];
    const float* bn3b  = (const float*)d_in[16];
    const float* bn3m  = (const float*)d_in[17];
    const float* bn3v  = (const float*)d_in[18];
    float* out = (float*)d_out;

    prep_kernel<<<(N9*CM*CM + 255)/256, 256>>>(cv1_w, off_w, dcn_w, cv3_w);
    k1_conv1<<<BSZ*100, 128>>>(x, bn1g, bn1b, bn1m, bn1v);
    k2_offsets<<<BSZ*25, 256>>>(off_b);

    int smem_bytes = K3_SMEM_F * 4;  // 51712 B
    cudaFuncSetAttribute(k3_deform_mma, cudaFuncAttributeMaxDynamicSharedMemorySize, smem_bytes);
    k3_deform_mma<<<BSZ*50, 256, smem_bytes>>>(dcn_b, bn2g, bn2b, bn2m, bn2v);

    k4_conv3<<<dim3(BSZ*100, 2), 128>>>(x, out, bn3g, bn3b, bn3m, bn3v);
}

// round 4
// speedup vs baseline: 1.5896x; 1.1861x over previous
#include <cuda_runtime.h>
#include <math.h>
#include <stdint.h>

#define BSZ   8
#define C1    256
#define C2    256
#define CM    128
#define Hh    80
#define Ww    80
#define HW    6400
#define N9    9
#define KCN   1152      // CM * 9
#define NOFF  27
#define EPSF  1e-5f

// ---------------- scratch (device globals; no runtime alloc) ----------------
__device__ __align__(16) float g_xT  [BSZ*HW*C1];     // NHWC transpose of x
__device__ __align__(16) float g_y   [BSZ*HW*CM];     // NHWC  y = silu(bn1(conv1))
__device__ __align__(16) float g_pred[BSZ*HW*NOFF];   // per-pixel [27]
__device__ __align__(16) float g_z   [BSZ*HW*CM];     // NHWC  deform+bn2+silu
__device__ __align__(16) float g_w2r [KCN*28];        // [(c*9+n)][oc pad 28]
__device__ __align__(16) float g_wd2 [N9*CM*CM];      // [n][o][c]

__device__ __forceinline__ float silu_f(float v){ return v / (1.f + __expf(-v)); }
__device__ __forceinline__ uint32_t f2tf32(float v){
    uint32_t t; asm("cvt.rna.tf32.f32 %0, %1;" : "=r"(t) : "f"(v));
    return t;
}

#define APAD 36
#define MMA_STEP(accq, a0,a1,a2,a3, b0,b1) \
    asm volatile("mma.sync.aligned.m16n8k8.row.col.f32.tf32.tf32.f32 " \
        "{%0,%1,%2,%3}, {%4,%5,%6,%7}, {%8,%9}, {%0,%1,%2,%3};" \
        : "+f"((accq)[0]), "+f"((accq)[1]), "+f"((accq)[2]), "+f"((accq)[3]) \
        : "r"(a0), "r"(a1), "r"(a2), "r"(a3), "r"(b0), "r"(b1))

// generic 128x128 warp-tiled mma on As[128][APAD], Bs[128][APAD] (tf32 bits)
// warp grid 4m x 2n; per warp: 2 m16 x 8 n8, acc[2][8][4]
__device__ __forceinline__ void mma_tile_128(const uint32_t* As, const uint32_t* Bs,
                                             int wm, int wnn, int gid, int tig,
                                             float acc[2][8][4]){
    const uint32_t* Ab = As + (wm*32 + gid)*APAD;
    const uint32_t* Bb = Bs + (wnn*64 + gid)*APAD;
    #pragma unroll
    for (int kk = 0; kk < 4; kk++){
        int kb = kk*8 + tig;
        uint32_t a[2][4];
        #pragma unroll
        for (int mt = 0; mt < 2; mt++){
            a[mt][0] = Ab[(mt*16)*APAD + kb];
            a[mt][1] = Ab[(mt*16+8)*APAD + kb];
            a[mt][2] = Ab[(mt*16)*APAD + kb + 4];
            a[mt][3] = Ab[(mt*16+8)*APAD + kb + 4];
        }
        #pragma unroll
        for (int nt = 0; nt < 8; nt++){
            uint32_t b0 = Bb[(nt*8)*APAD + kb];
            uint32_t b1 = Bb[(nt*8)*APAD + kb + 4];
            #pragma unroll
            for (int mt = 0; mt < 2; mt++)
                MMA_STEP(acc[mt][nt], a[mt][0],a[mt][1],a[mt][2],a[mt][3], b0,b1);
        }
    }
}

// ---------------- K0a: weight reshapes ----------------
__global__ void prep_w(const float* __restrict__ w2, const float* __restrict__ wd){
    int i = blockIdx.x*blockDim.x + threadIdx.x;
    if (i < KCN*28){ int k=i/28, oc=i%28; g_w2r[i] = (oc<NOFF) ? w2[oc*KCN + k] : 0.f; }
    if (i < N9*CM*CM){
        int n = i/(CM*CM); int rest = i%(CM*CM); int o = rest/CM, c = rest%CM;
        g_wd2[i] = wd[o*KCN + c*9 + n];
    }
}

// ---------------- K0b: x NCHW -> NHWC ----------------
__global__ void __launch_bounds__(256) prep_xT(const float* __restrict__ x){
    __shared__ float t[32][33];
    int b  = blockIdx.z;
    int c0 = blockIdx.y * 32;
    int p0 = blockIdx.x * 32;
    int tx = threadIdx.x & 31, ty = threadIdx.x >> 5;   // 32 x 8
    #pragma unroll
    for (int i = 0; i < 4; i++)
        t[ty + 8*i][tx] = x[((size_t)b*C1 + c0 + ty + 8*i)*HW + p0 + tx];
    __syncthreads();
    #pragma unroll
    for (int i = 0; i < 4; i++)
        g_xT[((size_t)b*HW + p0 + ty + 8*i)*C1 + c0 + tx] = t[tx][ty + 8*i];
}

// ---------------- K1: conv1x1(256->128) + bn1 + silu -> g_y (NHWC), tf32 mma ----------------
__global__ void __launch_bounds__(256, 2) k1_mma(const float* __restrict__ w1,
        const float* __restrict__ g1, const float* __restrict__ b1,
        const float* __restrict__ m1, const float* __restrict__ v1){
    __shared__ uint32_t As[128*APAD];
    __shared__ uint32_t Bs[128*APAD];
    __shared__ float sS[128], sT[128];
    int blk = blockIdx.x;
    int b_ = blk / 50;
    int p0 = (blk % 50) * 128;
    int tid = threadIdx.x, warp = tid >> 5, lane = tid & 31;
    int wm = warp & 3, wnn = warp >> 2, gid = lane >> 2, tig = lane & 3;
    if (tid < 128){
        float s = g1[tid] * rsqrtf(v1[tid] + EPSF);
        sS[tid] = s;
        sT[tid] = b1[tid] - m1[tid]*s;
    }
    float acc[2][8][4] = {};
    const float* xt = g_xT + (size_t)(b_*HW + p0)*C1;
    for (int kc = 0; kc < 8; kc++){
        int k0 = kc*32;
        #pragma unroll
        for (int i = 0; i < 16; i++){
            int e = i*256 + tid; int r = e >> 5, kk = e & 31;
            As[r*APAD + kk] = f2tf32(xt[(size_t)r*C1 + k0 + kk]);
            Bs[r*APAD + kk] = f2tf32(w1[r*C1 + k0 + kk]);
        }
        __syncthreads();
        mma_tile_128(As, Bs, wm, wnn, gid, tig, acc);
        __syncthreads();
    }
    #pragma unroll
    for (int mt = 0; mt < 2; mt++){
        int r0 = wm*32 + mt*16 + gid;
        float* z0 = g_y + (size_t)(b_*HW + p0 + r0)*CM;
        float* z1 = z0 + 8*CM;
        #pragma unroll
        for (int nt = 0; nt < 8; nt++){
            int cb = wnn*64 + nt*8 + 2*tig;
            float s0 = sS[cb], s1 = sS[cb+1], t0 = sT[cb], t1 = sT[cb+1];
            float2 v0, v1;
            v0.x = silu_f(acc[mt][nt][0]*s0 + t0);
            v0.y = silu_f(acc[mt][nt][1]*s1 + t1);
            v1.x = silu_f(acc[mt][nt][2]*s0 + t0);
            v1.y = silu_f(acc[mt][nt][3]*s1 + t1);
            *(float2*)(z0 + cb) = v0;
            *(float2*)(z1 + cb) = v1;
        }
    }
}

// ---------------- K2: conv3x3(128->27) on g_y -> g_pred ----------------
__global__ void __launch_bounds__(256) k2_offsets(const float* __restrict__ offb){
    __shared__ float ys[16*324];
    __shared__ float ws[16*9*28];
    int b_ = blockIdx.x / 25;
    int tile = blockIdx.x % 25;
    int th0 = (tile/5)*16, tw0 = (tile%5)*16;
    int tid = threadIdx.x, lx = tid & 15, ly = tid >> 4;
    float acc[27] = {};
    for (int c0 = 0; c0 < CM; c0 += 16){
        for (int s = tid; s < 324; s += 256){
            int sy = s/18 - 1 + th0, sx = s%18 - 1 + tw0;
            bool ok = (sy>=0 && sy<Hh && sx>=0 && sx<Ww);
            const float* src = &g_y[(size_t)(b_*HW + sy*Ww + sx)*CM + c0];
            #pragma unroll
            for (int cc = 0; cc < 16; cc++)
                ys[cc*324 + s] = ok ? src[cc] : 0.f;
        }
        for (int s = tid; s < 16*9*28; s += 256) ws[s] = g_w2r[c0*9*28 + s];
        __syncthreads();
        #pragma unroll 2
        for (int cc = 0; cc < 16; cc++){
            float yv[9];
            #pragma unroll
            for (int n = 0; n < 9; n++)
                yv[n] = ys[cc*324 + (ly + n/3)*18 + (lx + n%3)];
            #pragma unroll
            for (int n = 0; n < 9; n++){
                const float* wp = &ws[(cc*9 + n)*28];
                #pragma unroll
                for (int oc = 0; oc < 27; oc++) acc[oc] += yv[n]*wp[oc];
            }
        }
        __syncthreads();
    }
    size_t base = (size_t)(b_*HW + (th0+ly)*Ww + (tw0+lx)) * NOFF;
    #pragma unroll
    for (int ch = 0; ch < 27; ch++){
        float vv = acc[ch] + offb[ch];
        if (ch >= 18) vv = 1.f/(1.f + __expf(-vv));
        g_pred[base + ch] = vv;
    }
}

// ---------------- K3: deform conv via mma.sync tf32 -> g_z (NHWC) ----------------
// dynamic smem floats: As 128*36, Bs 128*36, idx 1152*4 (int), wt 1152*4, S 128, T 128
#define K3_F_AS   0
#define K3_F_BS   (128*APAD)
#define K3_F_IDX  (2*128*APAD)
#define K3_F_WT   (K3_F_IDX + 4608)
#define K3_F_S    (K3_F_WT + 4608)
#define K3_F_T    (K3_F_S + 128)
#define K3_SMEM_F (K3_F_T + 128)

__global__ void __launch_bounds__(256, 2) k3_deform_mma(const float* __restrict__ dcnb,
        const float* __restrict__ g2, const float* __restrict__ b2,
        const float* __restrict__ m2, const float* __restrict__ v2){
    extern __shared__ float sm[];
    uint32_t* As = (uint32_t*)(sm + K3_F_AS);
    uint32_t* Bs = (uint32_t*)(sm + K3_F_BS);
    int4*   sIdx = (int4*)(sm + K3_F_IDX);
    float4* sWt  = (float4*)(sm + K3_F_WT);
    float* sS = sm + K3_F_S;
    float* sT = sm + K3_F_T;

    int blk = blockIdx.x;
    int b_ = blk / 50;
    int p0 = (blk % 50) * 128;
    int tid = threadIdx.x, warp = tid >> 5, lane = tid & 31;

    // setup: precompute bilinear corner indices + mask/validity-folded weights
    for (int pr = tid; pr < 128*9; pr += 256){
        int p = pr / 9, nn = pr % 9;
        int pg = p0 + p, h = pg / Ww, w = pg % Ww;
        size_t pb = (size_t)(b_*HW + pg) * NOFF;
        float py = (float)(h - 1 + nn/3) + g_pred[pb + 2*nn];
        float qx = (float)(w - 1 + nn%3) + g_pred[pb + 2*nn + 1];
        float mk = g_pred[pb + 18 + nn];
        float y0f = floorf(py), x0f = floorf(qx);
        float wy = py - y0f, wx = qx - x0f;
        int iy0 = (int)y0f, ix0 = (int)x0f, iy1 = iy0 + 1, ix1 = ix0 + 1;
        float vy0 = (iy0 >= 0 && iy0 < Hh) ? 1.f : 0.f;
        float vy1 = (iy1 >= 0 && iy1 < Hh) ? 1.f : 0.f;
        float vx0 = (ix0 >= 0 && ix0 < Ww) ? 1.f : 0.f;
        float vx1 = (ix1 >= 0 && ix1 < Ww) ? 1.f : 0.f;
        int cy0 = min(max(iy0,0),Hh-1), cy1 = min(max(iy1,0),Hh-1);
        int cx0 = min(max(ix0,0),Ww-1), cx1 = min(max(ix1,0),Ww-1);
        int base = b_*HW;
        int4 id;
        id.x = (base + cy0*Ww + cx0)*CM;
        id.y = (base + cy0*Ww + cx1)*CM;
        id.z = (base + cy1*Ww + cx0)*CM;
        id.w = (base + cy1*Ww + cx1)*CM;
        float4 wt;
        wt.x = (1.f-wy)*(1.f-wx)*mk*vy0*vx0;
        wt.y = (1.f-wy)*wx      *mk*vy0*vx1;
        wt.z = wy*(1.f-wx)      *mk*vy1*vx0;
        wt.w = wy*wx            *mk*vy1*vx1;
        sIdx[pr] = id;
        sWt[pr]  = wt;
    }
    if (tid < 128){
        float s = g2[tid] * rsqrtf(v2[tid] + EPSF);
        sS[tid] = s;
        sT[tid] = dcnb[tid]*s + b2[tid] - m2[tid]*s;
    }
    __syncthreads();

    int wm = warp & 3, wnn = warp >> 2, gid = lane >> 2, tig = lane & 3;
    float acc[2][8][4] = {};

    for (int it = 0; it < 36; it++){
        int n  = it >> 2;
        int c0 = (it & 3) << 5;

        // fill Bs[o][k] (tf32), coalesced
        const float* wn = g_wd2 + n*(CM*CM) + c0;
        #pragma unroll
        for (int i = 0; i < 16; i++){
            int e = i*256 + tid;
            int o = e >> 5, k = e & 31;
            Bs[o*APAD + k] = f2tf32(wn[o*CM + k]);
        }
        // fill As[px][k]: warp-per-16px, lane = channel; precomputed idx/wt broadcast
        const float* yb = g_y + c0 + lane;
        #pragma unroll 4
        for (int r = 0; r < 16; r++){
            int px = warp*16 + r;
            int pr = px*9 + n;
            int4   id = sIdx[pr];
            float4 wt = sWt[pr];
            float v = wt.x*yb[id.x] + wt.y*yb[id.y] + wt.z*yb[id.z] + wt.w*yb[id.w];
            As[px*APAD + lane] = f2tf32(v);
        }
        __syncthreads();
        mma_tile_128(As, Bs, wm, wnn, gid, tig, acc);
        __syncthreads();
    }

    // epilogue: bn2 + silu, NHWC float2 stores
    #pragma unroll
    for (int mt = 0; mt < 2; mt++){
        int r0 = wm*32 + mt*16 + gid;
        float* z0 = g_z + (size_t)(b_*HW + p0 + r0)*CM;
        float* z1 = z0 + 8*CM;
        #pragma unroll
        for (int nt = 0; nt < 8; nt++){
            int cb = wnn*64 + nt*8 + 2*tig;
            float s0 = sS[cb], s1 = sS[cb+1], t0 = sT[cb], t1 = sT[cb+1];
            float2 v0, v1;
            v0.x = silu_f(acc[mt][nt][0]*s0 + t0);
            v0.y = silu_f(acc[mt][nt][1]*s1 + t1);
            v1.x = silu_f(acc[mt][nt][2]*s0 + t0);
            v1.y = silu_f(acc[mt][nt][3]*s1 + t1);
            *(float2*)(z0 + cb) = v0;
            *(float2*)(z1 + cb) = v1;
        }
    }
}

// ---------------- K4: conv1x1(128->256) + bn3 + silu + residual -> out (NCHW), tf32 mma ----------------
__global__ void __launch_bounds__(256, 2) k4_mma(const float* __restrict__ x, float* __restrict__ out,
        const float* __restrict__ w3,
        const float* __restrict__ g3, const float* __restrict__ b3,
        const float* __restrict__ m3, const float* __restrict__ v3){
    __shared__ uint32_t As[128*APAD];
    __shared__ uint32_t Bs[128*APAD];
    __shared__ float sS[128], sT[128];
    int blk = blockIdx.x;
    int b_ = blk / 50;
    int p0 = (blk % 50) * 128;
    int o0g = blockIdx.y * 128;
    int tid = threadIdx.x, warp = tid >> 5, lane = tid & 31;
    int wm = warp & 3, wnn = warp >> 2, gid = lane >> 2, tig = lane & 3;
    if (tid < 128){
        int o = o0g + tid;
        float s = g3[o] * rsqrtf(v3[o] + EPSF);
        sS[tid] = s;
        sT[tid] = b3[o] - m3[o]*s;
    }
    float acc[2][8][4] = {};
    const float* zt = g_z + (size_t)(b_*HW + p0)*CM;
    const float* wb = w3 + (size_t)o0g*CM;
    for (int kc = 0; kc < 4; kc++){
        int k0 = kc*32;
        #pragma unroll
        for (int i = 0; i < 16; i++){
            int e = i*256 + tid; int r = e >> 5, kk = e & 31;
            As[r*APAD + kk] = f2tf32(zt[(size_t)r*CM + k0 + kk]);
            Bs[r*APAD + kk] = f2tf32(wb[r*CM + k0 + kk]);
        }
        __syncthreads();
        mma_tile_128(As, Bs, wm, wnn, gid, tig, acc);
        __syncthreads();
    }
    #pragma unroll
    for (int mt = 0; mt < 2; mt++){
        int pg0 = p0 + wm*32 + mt*16 + gid;
        #pragma unroll
        for (int nt = 0; nt < 8; nt++){
            int o = o0g + wnn*64 + nt*8 + 2*tig;
            float s0 = sS[o - o0g], s1 = sS[o - o0g + 1];
            float t0 = sT[o - o0g], t1 = sT[o - o0g + 1];
            size_t i00 = ((size_t)b_*C2 + o)*HW + pg0;
            size_t i01 = i00 + HW;            // o+1
            out[i00]     = x[i00]     + silu_f(acc[mt][nt][0]*s0 + t0);
            out[i01]     = x[i01]     + silu_f(acc[mt][nt][1]*s1 + t1);
            out[i00 + 8] = x[i00 + 8] + silu_f(acc[mt][nt][2]*s0 + t0);
            out[i01 + 8] = x[i01 + 8] + silu_f(acc[mt][nt][3]*s1 + t1);
        }
    }
}

// ---------------- launch ----------------
extern "C" void kernel_launch(void* const* d_in, const int* in_sizes, int n_in,
                              void* d_out, int out_size){
    const float* x     = (const float*)d_in[0];
    const float* cv1_w = (const float*)d_in[1];
    const float* bn1g  = (const float*)d_in[2];
    const float* bn1b  = (const float*)d_in[3];
    const float* bn1m  = (const float*)d_in[4];
    const float* bn1v  = (const float*)d_in[5];
    const float* off_w = (const float*)d_in[6];
    const float* off_b = (const float*)d_in[7];
    const float* dcn_w = (const float*)d_in[8];
    const float* dcn_b = (const float*)d_in[9];
    const float* bn2g  = (const float*)d_in[10];
    const float* bn2b  = (const float*)d_in[11];
    const float* bn2m  = (const float*)d_in[12];
    const float* bn2v  = (const float*)d_in[13];
    const float* cv3_w = (const float*)d_in[14];
    const float* bn3g  = (const float*)d_in[15];
    const float* bn3b  = (const float*)d_in[16];
    const float* bn3m  = (const float*)d_in[17];
    const float* bn3v  = (const float*)d_in[18];
    float* out = (float*)d_out;

    prep_w<<<(N9*CM*CM + 255)/256, 256>>>(off_w, dcn_w);
    prep_xT<<<dim3(200, 8, 8), 256>>>(x);
    k1_mma<<<BSZ*50, 256>>>(cv1_w, bn1g, bn1b, bn1m, bn1v);
    k2_offsets<<<BSZ*25, 256>>>(off_b);

    int smem_bytes = K3_SMEM_F * 4;  // 74752 B
    cudaFuncSetAttribute(k3_deform_mma, cudaFuncAttributeMaxDynamicSharedMemorySize, smem_bytes);
    k3_deform_mma<<<BSZ*50, 256, smem_bytes>>>(dcn_b, bn2g, bn2b, bn2m, bn2v);

    k4_mma<<<dim3(BSZ*50, 2), 256>>>(x, out, cv3_w, bn3g, bn3b, bn3m, bn3v);
}

// round 6
// speedup vs baseline: 1.8916x; 1.1900x over previous
#include <cuda_runtime.h>
#include <math.h>
#include <stdint.h>

#define BSZ   8
#define C1    256
#define C2    256
#define CM    128
#define Hh    80
#define Ww    80
#define HW    6400
#define N9    9
#define KCN   1152      // CM * 9
#define NOFF  27
#define EPSF  1e-5f

// ---------------- scratch (device globals; no runtime alloc) ----------------
__device__ __align__(16) float g_y   [BSZ*HW*CM];     // NHWC  y = silu(bn1(conv1))
__device__ __align__(16) float g_pred[BSZ*HW*NOFF];   // per-pixel [27]
__device__ __align__(16) float g_z   [BSZ*HW*CM];     // NHWC  deform+bn2+silu
__device__ __align__(16) float g_w2o [N9*32*CM];      // [n][o pad 32][c]
__device__ __align__(16) float g_wd2 [N9*CM*CM];      // [n][o][c]

__device__ __forceinline__ float silu_f(float v){ return v / (1.f + __expf(-v)); }
__device__ __forceinline__ uint32_t f2tf32(float v){
    uint32_t t; asm("cvt.rna.tf32.f32 %0, %1;" : "=r"(t) : "f"(v));
    return t;
}

#define APAD 36
#define MMA_STEP(accq, a0,a1,a2,a3, b0,b1) \
    asm volatile("mma.sync.aligned.m16n8k8.row.col.f32.tf32.tf32.f32 " \
        "{%0,%1,%2,%3}, {%4,%5,%6,%7}, {%8,%9}, {%0,%1,%2,%3};" \
        : "+f"((accq)[0]), "+f"((accq)[1]), "+f"((accq)[2]), "+f"((accq)[3]) \
        : "r"(a0), "r"(a1), "r"(a2), "r"(a3), "r"(b0), "r"(b1))

// generic 128x128 warp-tiled mma on As[128][APAD], Bs[128][APAD] (tf32 bits)
__device__ __forceinline__ void mma_tile_128(const uint32_t* As, const uint32_t* Bs,
                                             int wm, int wnn, int gid, int tig,
                                             float acc[2][8][4]){
    const uint32_t* Ab = As + (wm*32 + gid)*APAD;
    const uint32_t* Bb = Bs + (wnn*64 + gid)*APAD;
    #pragma unroll
    for (int kk = 0; kk < 4; kk++){
        int kb = kk*8 + tig;
        uint32_t a[2][4];
        #pragma unroll
        for (int mt = 0; mt < 2; mt++){
            a[mt][0] = Ab[(mt*16)*APAD + kb];
            a[mt][1] = Ab[(mt*16+8)*APAD + kb];
            a[mt][2] = Ab[(mt*16)*APAD + kb + 4];
            a[mt][3] = Ab[(mt*16+8)*APAD + kb + 4];
        }
        #pragma unroll
        for (int nt = 0; nt < 8; nt++){
            uint32_t b0 = Bb[(nt*8)*APAD + kb];
            uint32_t b1 = Bb[(nt*8)*APAD + kb + 4];
            #pragma unroll
            for (int mt = 0; mt < 2; mt++)
                MMA_STEP(acc[mt][nt], a[mt][0],a[mt][1],a[mt][2],a[mt][3], b0,b1);
        }
    }
}

// ---------------- K0: weight reshapes ----------------
__global__ void prep_w(const float* __restrict__ w2, const float* __restrict__ wd){
    int i = blockIdx.x*blockDim.x + threadIdx.x;
    if (i < N9*32*CM){
        int n = i/(32*CM); int o = (i/CM) & 31; int c = i % CM;
        g_w2o[i] = (o < NOFF) ? w2[o*KCN + c*9 + n] : 0.f;
    }
    if (i < N9*CM*CM){
        int n = i/(CM*CM); int rest = i%(CM*CM); int o = rest/CM, c = rest%CM;
        g_wd2[i] = wd[o*KCN + c*9 + n];
    }
}

// ---------------- K1: conv1x1(256->128) + bn1 + silu -> g_y (NHWC), tf32 mma ----------------
__global__ void __launch_bounds__(256, 2) k1_mma(const float* __restrict__ x,
        const float* __restrict__ w1,
        const float* __restrict__ g1, const float* __restrict__ b1,
        const float* __restrict__ m1, const float* __restrict__ v1){
    __shared__ uint32_t As[128*APAD];
    __shared__ uint32_t Bs[128*APAD];
    __shared__ float sS[128], sT[128];
    int blk = blockIdx.x;
    int b_ = blk / 50;
    int p0 = (blk % 50) * 128;
    int tid = threadIdx.x, warp = tid >> 5, lane = tid & 31;
    int wm = warp & 3, wnn = warp >> 2, gid = lane >> 2, tig = lane & 3;
    if (tid < 128){
        float s = g1[tid] * rsqrtf(v1[tid] + EPSF);
        sS[tid] = s;
        sT[tid] = b1[tid] - m1[tid]*s;
    }
    float acc[2][8][4] = {};
    const float* xb = x + (size_t)b_*C1*HW + p0;
    for (int kc = 0; kc < 8; kc++){
        int k0 = kc*32;
        // A: direct NCHW load, lane -> pixel (coalesced); smem store stride 36 (4-way)
        #pragma unroll
        for (int i = 0; i < 16; i++){
            int e = i*256 + tid; int kk = e >> 7, px = e & 127;
            As[px*APAD + kk] = f2tf32(xb[(size_t)(k0+kk)*HW + px]);
        }
        #pragma unroll
        for (int i = 0; i < 16; i++){
            int e = i*256 + tid; int r = e >> 5, kk = e & 31;
            Bs[r*APAD + kk] = f2tf32(w1[r*C1 + k0 + kk]);
        }
        __syncthreads();
        mma_tile_128(As, Bs, wm, wnn, gid, tig, acc);
        __syncthreads();
    }
    #pragma unroll
    for (int mt = 0; mt < 2; mt++){
        int r0 = wm*32 + mt*16 + gid;
        float* z0 = g_y + (size_t)(b_*HW + p0 + r0)*CM;
        float* z1 = z0 + 8*CM;
        #pragma unroll
        for (int nt = 0; nt < 8; nt++){
            int cb = wnn*64 + nt*8 + 2*tig;
            float s0 = sS[cb], s1 = sS[cb+1], t0 = sT[cb], t1 = sT[cb+1];
            float2 v0, v1;
            v0.x = silu_f(acc[mt][nt][0]*s0 + t0);
            v0.y = silu_f(acc[mt][nt][1]*s1 + t1);
            v1.x = silu_f(acc[mt][nt][2]*s0 + t0);
            v1.y = silu_f(acc[mt][nt][3]*s1 + t1);
            *(float2*)(z0 + cb) = v0;
            *(float2*)(z1 + cb) = v1;
        }
    }
}

// ---------------- K2: conv3x3(128->27) via tf32 mma (implicit im2col) -> g_pred ----------------
__global__ void __launch_bounds__(256, 4) k2_mma(const float* __restrict__ offb){
    __shared__ uint32_t As[128*APAD];
    __shared__ uint32_t Bs[32*APAD];
    __shared__ float sB[32];
    int blk = blockIdx.x;
    int b_ = blk / 50;
    int p0 = (blk % 50) * 128;
    int tid = threadIdx.x, warp = tid >> 5, lane = tid & 31;
    int gid = lane >> 2, tig = lane & 3;
    if (tid < 32) sB[tid] = (tid < NOFF) ? offb[tid] : 0.f;

    float acc[4][4] = {};
    for (int it = 0; it < 36; it++){
        int n  = it >> 2;
        int c0 = (it & 3) << 5;
        int dy = n/3 - 1, dx = n%3 - 1;
        // B: 32o x 32k
        #pragma unroll
        for (int i = 0; i < 4; i++){
            int e = i*256 + tid; int o = e >> 5, k = e & 31;
            Bs[o*APAD + k] = f2tf32(g_w2o[(n*32 + o)*CM + c0 + k]);
        }
        // A: im2col from NHWC g_y, warp per 16 px, lane = channel
        #pragma unroll 4
        for (int r = 0; r < 16; r++){
            int px = warp*16 + r;
            int pg = p0 + px, h = pg / Ww, w = pg % Ww;
            int sy = h + dy, sx = w + dx;
            bool ok = (sy >= 0) & (sy < Hh) & (sx >= 0) & (sx < Ww);
            float v = ok ? g_y[(size_t)(b_*HW + sy*Ww + sx)*CM + c0 + lane] : 0.f;
            As[px*APAD + lane] = f2tf32(v);
        }
        __syncthreads();
        const uint32_t* Ab = As + (warp*16 + gid)*APAD;
        const uint32_t* Bb = Bs + gid*APAD;
        #pragma unroll
        for (int kk = 0; kk < 4; kk++){
            int kb = kk*8 + tig;
            uint32_t a0 = Ab[kb], a1 = Ab[8*APAD + kb];
            uint32_t a2 = Ab[kb + 4], a3 = Ab[8*APAD + kb + 4];
            #pragma unroll
            for (int nt = 0; nt < 4; nt++){
                uint32_t b0 = Bb[(nt*8)*APAD + kb];
                uint32_t b1 = Bb[(nt*8)*APAD + kb + 4];
                MMA_STEP(acc[nt], a0,a1,a2,a3, b0,b1);
            }
        }
        __syncthreads();
    }
    // epilogue: +bias, sigmoid for ch>=18, write [27] per pixel
    #pragma unroll
    for (int half = 0; half < 2; half++){
        int px = warp*16 + gid + half*8;
        float* pp = g_pred + (size_t)(b_*HW + p0 + px)*NOFF;
        #pragma unroll
        for (int nt = 0; nt < 4; nt++){
            int c = nt*8 + 2*tig;
            float v0 = acc[nt][half*2 + 0] + sB[c];
            float v1 = acc[nt][half*2 + 1] + sB[c+1];
            if (c >= 18)   v0 = 1.f/(1.f + __expf(-v0));
            if (c+1 >= 18) v1 = 1.f/(1.f + __expf(-v1));
            if (c < NOFF)   pp[c]   = v0;
            if (c+1 < NOFF) pp[c+1] = v1;
        }
    }
}

// ---------------- K3: deform conv via mma.sync tf32 -> g_z (NHWC) ----------------
#define K3_F_AS   0
#define K3_F_BS   (128*APAD)
#define K3_F_IDX  (2*128*APAD)
#define K3_F_WT   (K3_F_IDX + 4608)
#define K3_F_S    (K3_F_WT + 4608)
#define K3_F_T    (K3_F_S + 128)
#define K3_SMEM_F (K3_F_T + 128)

__global__ void __launch_bounds__(256, 2) k3_deform_mma(const float* __restrict__ dcnb,
        const float* __restrict__ g2, const float* __restrict__ b2,
        const float* __restrict__ m2, const float* __restrict__ v2){
    extern __shared__ float sm[];
    uint32_t* As = (uint32_t*)(sm + K3_F_AS);
    uint32_t* Bs = (uint32_t*)(sm + K3_F_BS);
    int4*   sIdx = (int4*)(sm + K3_F_IDX);
    float4* sWt  = (float4*)(sm + K3_F_WT);
    float* sS = sm + K3_F_S;
    float* sT = sm + K3_F_T;

    int blk = blockIdx.x;
    int b_ = blk / 50;
    int p0 = (blk % 50) * 128;
    int tid = threadIdx.x, warp = tid >> 5, lane = tid & 31;

    for (int pr = tid; pr < 128*9; pr += 256){
        int p = pr / 9, nn = pr % 9;
        int pg = p0 + p, h = pg / Ww, w = pg % Ww;
        size_t pb = (size_t)(b_*HW + pg) * NOFF;
        float py = (float)(h - 1 + nn/3) + g_pred[pb + 2*nn];
        float qx = (float)(w - 1 + nn%3) + g_pred[pb + 2*nn + 1];
        float mk = g_pred[pb + 18 + nn];
        float y0f = floorf(py), x0f = floorf(qx);
        float wy = py - y0f, wx = qx - x0f;
        int iy0 = (int)y0f, ix0 = (int)x0f, iy1 = iy0 + 1, ix1 = ix0 + 1;
        float vy0 = (iy0 >= 0 && iy0 < Hh) ? 1.f : 0.f;
        float vy1 = (iy1 >= 0 && iy1 < Hh) ? 1.f : 0.f;
        float vx0 = (ix0 >= 0 && ix0 < Ww) ? 1.f : 0.f;
        float vx1 = (ix1 >= 0 && ix1 < Ww) ? 1.f : 0.f;
        int cy0 = min(max(iy0,0),Hh-1), cy1 = min(max(iy1,0),Hh-1);
        int cx0 = min(max(ix0,0),Ww-1), cx1 = min(max(ix1,0),Ww-1);
        int base = b_*HW;
        int4 id;
        id.x = (base + cy0*Ww + cx0)*CM;
        id.y = (base + cy0*Ww + cx1)*CM;
        id.z = (base + cy1*Ww + cx0)*CM;
        id.w = (base + cy1*Ww + cx1)*CM;
        float4 wt;
        wt.x = (1.f-wy)*(1.f-wx)*mk*vy0*vx0;
        wt.y = (1.f-wy)*wx      *mk*vy0*vx1;
        wt.z = wy*(1.f-wx)      *mk*vy1*vx0;
        wt.w = wy*wx            *mk*vy1*vx1;
        sIdx[pr] = id;
        sWt[pr]  = wt;
    }
    if (tid < 128){
        float s = g2[tid] * rsqrtf(v2[tid] + EPSF);
        sS[tid] = s;
        sT[tid] = dcnb[tid]*s + b2[tid] - m2[tid]*s;
    }
    __syncthreads();

    int wm = warp & 3, wnn = warp >> 2, gid = lane >> 2, tig = lane & 3;
    float acc[2][8][4] = {};

    for (int it = 0; it < 36; it++){
        int n  = it >> 2;
        int c0 = (it & 3) << 5;
        const float* wn = g_wd2 + n*(CM*CM) + c0;
        #pragma unroll
        for (int i = 0; i < 16; i++){
            int e = i*256 + tid;
            int o = e >> 5, k = e & 31;
            Bs[o*APAD + k] = f2tf32(wn[o*CM + k]);
        }
        const float* yb = g_y + c0 + lane;
        #pragma unroll 4
        for (int r = 0; r < 16; r++){
            int px = warp*16 + r;
            int pr = px*9 + n;
            int4   id = sIdx[pr];
            float4 wt = sWt[pr];
            float v = wt.x*yb[id.x] + wt.y*yb[id.y] + wt.z*yb[id.z] + wt.w*yb[id.w];
            As[px*APAD + lane] = f2tf32(v);
        }
        __syncthreads();
        mma_tile_128(As, Bs, wm, wnn, gid, tig, acc);
        __syncthreads();
    }

    #pragma unroll
    for (int mt = 0; mt < 2; mt++){
        int r0 = wm*32 + mt*16 + gid;
        float* z0 = g_z + (size_t)(b_*HW + p0 + r0)*CM;
        float* z1 = z0 + 8*CM;
        #pragma unroll
        for (int nt = 0; nt < 8; nt++){
            int cb = wnn*64 + nt*8 + 2*tig;
            float s0 = sS[cb], s1 = sS[cb+1], t0 = sT[cb], t1 = sT[cb+1];
            float2 v0, v1;
            v0.x = silu_f(acc[mt][nt][0]*s0 + t0);
            v0.y = silu_f(acc[mt][nt][1]*s1 + t1);
            v1.x = silu_f(acc[mt][nt][2]*s0 + t0);
            v1.y = silu_f(acc[mt][nt][3]*s1 + t1);
            *(float2*)(z0 + cb) = v0;
            *(float2*)(z1 + cb) = v1;
        }
    }
}

// ---------------- K4: conv1x1(128->256) + bn3 + silu + residual -> out (NCHW), tf32 mma ----------------
__global__ void __launch_bounds__(256, 2) k4_mma(const float* __restrict__ x, float* __restrict__ out,
        const float* __restrict__ w3,
        const float* __restrict__ g3, const float* __restrict__ b3,
        const float* __restrict__ m3, const float* __restrict__ v3){
    __shared__ uint32_t As[128*APAD];
    __shared__ uint32_t Bs[128*APAD];
    __shared__ float sS[128], sT[128];
    int blk = blockIdx.x;
    int b_ = blk / 50;
    int p0 = (blk % 50) * 128;
    int o0g = blockIdx.y * 128;
    int tid = threadIdx.x, warp = tid >> 5, lane = tid & 31;
    int wm = warp & 3, wnn = warp >> 2, gid = lane >> 2, tig = lane & 3;
    if (tid < 128){
        int o = o0g + tid;
        float s = g3[o] * rsqrtf(v3[o] + EPSF);
        sS[tid] = s;
        sT[tid] = b3[o] - m3[o]*s;
    }
    float acc[2][8][4] = {};
    const float* zt = g_z + (size_t)(b_*HW + p0)*CM;
    const float* wb = w3 + (size_t)o0g*CM;
    for (int kc = 0; kc < 4; kc++){
        int k0 = kc*32;
        #pragma unroll
        for (int i = 0; i < 16; i++){
            int e = i*256 + tid; int r = e >> 5, kk = e & 31;
            As[r*APAD + kk] = f2tf32(zt[(size_t)r*CM + k0 + kk]);
            Bs[r*APAD + kk] = f2tf32(wb[r*CM + k0 + kk]);
        }
        __syncthreads();
        mma_tile_128(As, Bs, wm, wnn, gid, tig, acc);
        __syncthreads();
    }
    #pragma unroll
    for (int mt = 0; mt < 2; mt++){
        int pg0 = p0 + wm*32 + mt*16 + gid;
        #pragma unroll
        for (int nt = 0; nt < 8; nt++){
            int o = o0g + wnn*64 + nt*8 + 2*tig;
            float s0 = sS[o - o0g], s1 = sS[o - o0g + 1];
            float t0 = sT[o - o0g], t1 = sT[o - o0g + 1];
            size_t i00 = ((size_t)b_*C2 + o)*HW + pg0;
            size_t i01 = i00 + HW;
            out[i00]     = x[i00]     + silu_f(acc[mt][nt][0]*s0 + t0);
            out[i01]     = x[i01]     + silu_f(acc[mt][nt][1]*s1 + t1);
            out[i00 + 8] = x[i00 + 8] + silu_f(acc[mt][nt][2]*s0 + t0);
            out[i01 + 8] = x[i01 + 8] + silu_f(acc[mt][nt][3]*s1 + t1);
        }
    }
}

// ---------------- launch ----------------
extern "C" void kernel_launch(void* const* d_in, const int* in_sizes, int n_in,
                              void* d_out, int out_size){
    const float* x     = (const float*)d_in[0];
    const float* cv1_w = (const float*)d_in[1];
    const float* bn1g  = (const float*)d_in[2];
    const float* bn1b  = (const float*)d_in[3];
    const float* bn1m  = (const float*)d_in[4];
    const float* bn1v  = (const float*)d_in[5];
    const float* off_w = (const float*)d_in[6];
    const float* off_b = (const float*)d_in[7];
    const float* dcn_w = (const float*)d_in[8];
    const float* dcn_b = (const float*)d_in[9];
    const float* bn2g  = (const float*)d_in[10];
    const float* bn2b  = (const float*)d_in[11];
    const float* bn2m  = (const float*)d_in[12];
    const float* bn2v  = (const float*)d_in[13];
    const float* cv3_w = (const float*)d_in[14];
    const float* bn3g  = (const float*)d_in[15];
    const float* bn3b  = (const float*)d_in[16];
    const float* bn3m  = (const float*)d_in[17];
    const float* bn3v  = (const float*)d_in[18];
    float* out = (float*)d_out;

    prep_w<<<(N9*CM*CM + 255)/256, 256>>>(off_w, dcn_w);
    k1_mma<<<BSZ*50, 256>>>(x, cv1_w, bn1g, bn1b, bn1m, bn1v);
    k2_mma<<<BSZ*50, 256>>>(off_b);

    int smem_bytes = K3_SMEM_F * 4;  // 74752 B
    cudaFuncSetAttribute(k3_deform_mma, cudaFuncAttributeMaxDynamicSharedMemorySize, smem_bytes);
    k3_deform_mma<<<BSZ*50, 256, smem_bytes>>>(dcn_b, bn2g, bn2b, bn2m, bn2v);

    k4_mma<<<dim3(BSZ*50, 2), 256>>>(x, out, cv3_w, bn3g, bn3b, bn3m, bn3v);
}

// round 7
// speedup vs baseline: 1.9998x; 1.0572x over previous
#include <cuda_runtime.h>
#include <math.h>
#include <stdint.h>

#define BSZ   8
#define C1    256
#define C2    256
#define CM    128
#define Hh    80
#define Ww    80
#define HW    6400
#define N9    9
#define KCN   1152      // CM * 9
#define NOFF  27
#define EPSF  1e-5f

// ---------------- scratch (device globals; no runtime alloc) ----------------
__device__ __align__(16) float g_y   [BSZ*HW*CM];     // NHWC  y = silu(bn1(conv1))
__device__ __align__(16) float g_pred[BSZ*HW*NOFF];   // per-pixel [27]
__device__ __align__(16) float g_z   [BSZ*HW*CM];     // NHWC  deform+bn2+silu
__device__ __align__(16) float g_w2o [N9*32*CM];      // [n][o pad 32][c]
__device__ __align__(16) float g_wd2 [N9*CM*CM];      // [n][o][c]

__device__ __forceinline__ float silu_f(float v){ return v / (1.f + __expf(-v)); }
__device__ __forceinline__ uint32_t f2tf32(float v){
    uint32_t t; asm("cvt.rna.tf32.f32 %0, %1;" : "=r"(t) : "f"(v));
    return t;
}
__device__ __forceinline__ uint32_t s2u(const void* p){
    return (uint32_t)__cvta_generic_to_shared(p);
}
__device__ __forceinline__ void cpa16(uint32_t s, const void* g){
    asm volatile("cp.async.cg.shared.global [%0], [%1], 16;" :: "r"(s), "l"(g));
}
#define CPA_COMMIT() asm volatile("cp.async.commit_group;" ::: "memory")
#define CPA_WAIT0()  asm volatile("cp.async.wait_group 0;" ::: "memory")

#define APAD 36
#define MMA_STEP(accq, a0,a1,a2,a3, b0,b1) \
    asm volatile("mma.sync.aligned.m16n8k8.row.col.f32.tf32.tf32.f32 " \
        "{%0,%1,%2,%3}, {%4,%5,%6,%7}, {%8,%9}, {%0,%1,%2,%3};" \
        : "+f"((accq)[0]), "+f"((accq)[1]), "+f"((accq)[2]), "+f"((accq)[3]) \
        : "r"(a0), "r"(a1), "r"(a2), "r"(a3), "r"(b0), "r"(b1))

// generic 128x128 warp-tiled mma on As[128][APAD], Bs[128][APAD] (tf32 bits)
__device__ __forceinline__ void mma_tile_128(const uint32_t* As, const uint32_t* Bs,
                                             int wm, int wnn, int gid, int tig,
                                             float acc[2][8][4]){
    const uint32_t* Ab = As + (wm*32 + gid)*APAD;
    const uint32_t* Bb = Bs + (wnn*64 + gid)*APAD;
    #pragma unroll
    for (int kk = 0; kk < 4; kk++){
        int kb = kk*8 + tig;
        uint32_t a[2][4];
        #pragma unroll
        for (int mt = 0; mt < 2; mt++){
            a[mt][0] = Ab[(mt*16)*APAD + kb];
            a[mt][1] = Ab[(mt*16+8)*APAD + kb];
            a[mt][2] = Ab[(mt*16)*APAD + kb + 4];
            a[mt][3] = Ab[(mt*16+8)*APAD + kb + 4];
        }
        #pragma unroll
        for (int nt = 0; nt < 8; nt++){
            uint32_t b0 = Bb[(nt*8)*APAD + kb];
            uint32_t b1 = Bb[(nt*8)*APAD + kb + 4];
            #pragma unroll
            for (int mt = 0; mt < 2; mt++)
                MMA_STEP(acc[mt][nt], a[mt][0],a[mt][1],a[mt][2],a[mt][3], b0,b1);
        }
    }
}

// ---------------- K0: weight reshapes ----------------
__global__ void prep_w(const float* __restrict__ w2, const float* __restrict__ wd){
    int i = blockIdx.x*blockDim.x + threadIdx.x;
    if (i < N9*32*CM){
        int n = i/(32*CM); int o = (i/CM) & 31; int c = i % CM;
        g_w2o[i] = (o < NOFF) ? w2[o*KCN + c*9 + n] : 0.f;
    }
    if (i < N9*CM*CM){
        int n = i/(CM*CM); int rest = i%(CM*CM); int o = rest/CM, c = rest%CM;
        g_wd2[i] = wd[o*KCN + c*9 + n];
    }
}

// ---------------- K1: conv1x1(256->128) + bn1 + silu -> g_y (NHWC), tf32 mma ----------------
__global__ void __launch_bounds__(256, 2) k1_mma(const float* __restrict__ x,
        const float* __restrict__ w1,
        const float* __restrict__ g1, const float* __restrict__ b1,
        const float* __restrict__ m1, const float* __restrict__ v1){
    __shared__ __align__(16) uint32_t As[128*APAD];
    __shared__ __align__(16) uint32_t Bs[128*APAD];
    __shared__ float sS[128], sT[128];
    int blk = blockIdx.x;
    int b_ = blk / 50;
    int p0 = (blk % 50) * 128;
    int tid = threadIdx.x, warp = tid >> 5, lane = tid & 31;
    int wm = warp & 3, wnn = warp >> 2, gid = lane >> 2, tig = lane & 3;
    if (tid < 128){
        float s = g1[tid] * rsqrtf(v1[tid] + EPSF);
        sS[tid] = s;
        sT[tid] = b1[tid] - m1[tid]*s;
    }
    float acc[2][8][4] = {};
    const float* xb = x + (size_t)b_*C1*HW + p0;
    uint32_t bsu = s2u(Bs);
    for (int kc = 0; kc < 8; kc++){
        int k0 = kc*32;
        // B: cp.async 16B, raw fp32 (HW tf32-truncates)
        #pragma unroll
        for (int i = 0; i < 4; i++){
            int u = i*256 + tid; int r = u >> 3, seg = u & 7;
            cpa16(bsu + (r*APAD + seg*4)*4, w1 + r*C1 + k0 + seg*4);
        }
        CPA_COMMIT();
        // A: NCHW transpose load, lane -> pixel (coalesced)
        #pragma unroll
        for (int i = 0; i < 16; i++){
            int e = i*256 + tid; int kk = e >> 7, px = e & 127;
            As[px*APAD + kk] = f2tf32(xb[(size_t)(k0+kk)*HW + px]);
        }
        CPA_WAIT0();
        __syncthreads();
        mma_tile_128(As, Bs, wm, wnn, gid, tig, acc);
        __syncthreads();
    }
    #pragma unroll
    for (int mt = 0; mt < 2; mt++){
        int r0 = wm*32 + mt*16 + gid;
        float* z0 = g_y + (size_t)(b_*HW + p0 + r0)*CM;
        float* z1 = z0 + 8*CM;
        #pragma unroll
        for (int nt = 0; nt < 8; nt++){
            int cb = wnn*64 + nt*8 + 2*tig;
            float s0 = sS[cb], s1 = sS[cb+1], t0 = sT[cb], t1 = sT[cb+1];
            float2 v0, v1;
            v0.x = silu_f(acc[mt][nt][0]*s0 + t0);
            v0.y = silu_f(acc[mt][nt][1]*s1 + t1);
            v1.x = silu_f(acc[mt][nt][2]*s0 + t0);
            v1.y = silu_f(acc[mt][nt][3]*s1 + t1);
            *(float2*)(z0 + cb) = v0;
            *(float2*)(z1 + cb) = v1;
        }
    }
}

// ---------------- K2: conv3x3(128->27) via tf32 mma (implicit im2col) -> g_pred ----------------
__global__ void __launch_bounds__(256, 4) k2_mma(const float* __restrict__ offb){
    __shared__ __align__(16) uint32_t As[128*APAD];
    __shared__ __align__(16) uint32_t Bs[32*APAD];
    __shared__ float sB[32];
    int blk = blockIdx.x;
    int b_ = blk / 50;
    int p0 = (blk % 50) * 128;
    int tid = threadIdx.x, warp = tid >> 5, lane = tid & 31;
    int gid = lane >> 2, tig = lane & 3;
    if (tid < 32) sB[tid] = (tid < NOFF) ? offb[tid] : 0.f;

    float acc[4][4] = {};
    for (int it = 0; it < 36; it++){
        int n  = it >> 2;
        int c0 = (it & 3) << 5;
        int dy = n/3 - 1, dx = n%3 - 1;
        #pragma unroll
        for (int i = 0; i < 4; i++){
            int e = i*256 + tid; int o = e >> 5, k = e & 31;
            Bs[o*APAD + k] = f2tf32(g_w2o[(n*32 + o)*CM + c0 + k]);
        }
        #pragma unroll 4
        for (int r = 0; r < 16; r++){
            int px = warp*16 + r;
            int pg = p0 + px, h = pg / Ww, w = pg % Ww;
            int sy = h + dy, sx = w + dx;
            bool ok = (sy >= 0) & (sy < Hh) & (sx >= 0) & (sx < Ww);
            float v = ok ? g_y[(size_t)(b_*HW + sy*Ww + sx)*CM + c0 + lane] : 0.f;
            As[px*APAD + lane] = f2tf32(v);
        }
        __syncthreads();
        const uint32_t* Ab = As + (warp*16 + gid)*APAD;
        const uint32_t* Bb = Bs + gid*APAD;
        #pragma unroll
        for (int kk = 0; kk < 4; kk++){
            int kb = kk*8 + tig;
            uint32_t a0 = Ab[kb], a1 = Ab[8*APAD + kb];
            uint32_t a2 = Ab[kb + 4], a3 = Ab[8*APAD + kb + 4];
            #pragma unroll
            for (int nt = 0; nt < 4; nt++){
                uint32_t b0 = Bb[(nt*8)*APAD + kb];
                uint32_t b1 = Bb[(nt*8)*APAD + kb + 4];
                MMA_STEP(acc[nt], a0,a1,a2,a3, b0,b1);
            }
        }
        __syncthreads();
    }
    #pragma unroll
    for (int half = 0; half < 2; half++){
        int px = warp*16 + gid + half*8;
        float* pp = g_pred + (size_t)(b_*HW + p0 + px)*NOFF;
        #pragma unroll
        for (int nt = 0; nt < 4; nt++){
            int c = nt*8 + 2*tig;
            float v0 = acc[nt][half*2 + 0] + sB[c];
            float v1 = acc[nt][half*2 + 1] + sB[c+1];
            if (c >= 18)   v0 = 1.f/(1.f + __expf(-v0));
            if (c+1 >= 18) v1 = 1.f/(1.f + __expf(-v1));
            if (c < NOFF)   pp[c]   = v0;
            if (c+1 < NOFF) pp[c+1] = v1;
        }
    }
}

// ---------------- K3: deform conv via mma.sync tf32, double-buffered pipeline ----------------
#define K3_F_AS0  0
#define K3_F_AS1  (128*APAD)
#define K3_F_BS0  (2*128*APAD)
#define K3_F_BS1  (3*128*APAD)
#define K3_F_IDX  (4*128*APAD)
#define K3_F_WT   (K3_F_IDX + 4608)
#define K3_F_S    (K3_F_WT + 4608)
#define K3_F_T    (K3_F_S + 128)
#define K3_SMEM_F (K3_F_T + 128)

__global__ void __launch_bounds__(256, 2) k3_deform_mma(const float* __restrict__ dcnb,
        const float* __restrict__ g2, const float* __restrict__ b2,
        const float* __restrict__ m2, const float* __restrict__ v2){
    extern __shared__ float sm[];
    uint32_t* AsB[2] = { (uint32_t*)(sm + K3_F_AS0), (uint32_t*)(sm + K3_F_AS1) };
    uint32_t* BsB[2] = { (uint32_t*)(sm + K3_F_BS0), (uint32_t*)(sm + K3_F_BS1) };
    int4*   sIdx = (int4*)(sm + K3_F_IDX);
    float4* sWt  = (float4*)(sm + K3_F_WT);
    float* sS = sm + K3_F_S;
    float* sT = sm + K3_F_T;

    int blk = blockIdx.x;
    int b_ = blk / 50;
    int p0 = (blk % 50) * 128;
    int tid = threadIdx.x, warp = tid >> 5, lane = tid & 31;

    // setup: precompute bilinear corner indices + mask/validity-folded weights
    for (int pr = tid; pr < 128*9; pr += 256){
        int p = pr / 9, nn = pr % 9;
        int pg = p0 + p, h = pg / Ww, w = pg % Ww;
        size_t pb = (size_t)(b_*HW + pg) * NOFF;
        float py = (float)(h - 1 + nn/3) + g_pred[pb + 2*nn];
        float qx = (float)(w - 1 + nn%3) + g_pred[pb + 2*nn + 1];
        float mk = g_pred[pb + 18 + nn];
        float y0f = floorf(py), x0f = floorf(qx);
        float wy = py - y0f, wx = qx - x0f;
        int iy0 = (int)y0f, ix0 = (int)x0f, iy1 = iy0 + 1, ix1 = ix0 + 1;
        float vy0 = (iy0 >= 0 && iy0 < Hh) ? 1.f : 0.f;
        float vy1 = (iy1 >= 0 && iy1 < Hh) ? 1.f : 0.f;
        float vx0 = (ix0 >= 0 && ix0 < Ww) ? 1.f : 0.f;
        float vx1 = (ix1 >= 0 && ix1 < Ww) ? 1.f : 0.f;
        int cy0 = min(max(iy0,0),Hh-1), cy1 = min(max(iy1,0),Hh-1);
        int cx0 = min(max(ix0,0),Ww-1), cx1 = min(max(ix1,0),Ww-1);
        int base = b_*HW;
        int4 id;
        id.x = (base + cy0*Ww + cx0)*CM;
        id.y = (base + cy0*Ww + cx1)*CM;
        id.z = (base + cy1*Ww + cx0)*CM;
        id.w = (base + cy1*Ww + cx1)*CM;
        float4 wt;
        wt.x = (1.f-wy)*(1.f-wx)*mk*vy0*vx0;
        wt.y = (1.f-wy)*wx      *mk*vy0*vx1;
        wt.z = wy*(1.f-wx)      *mk*vy1*vx0;
        wt.w = wy*wx            *mk*vy1*vx1;
        sIdx[pr] = id;
        sWt[pr]  = wt;
    }
    if (tid < 128){
        float s = g2[tid] * rsqrtf(v2[tid] + EPSF);
        sS[tid] = s;
        sT[tid] = dcnb[tid]*s + b2[tid] - m2[tid]*s;
    }
    __syncthreads();

    int wm = warp & 3, wnn = warp >> 2, gid = lane >> 2, tig = lane & 3;
    float acc[2][8][4] = {};

    // ---- fill helpers (lambdas) ----
    auto fillB = [&](int it, int buf){
        int n = it >> 2, c0 = (it & 3) << 5;
        const float* wn = g_wd2 + n*(CM*CM) + c0;
        uint32_t bu = s2u(BsB[buf]);
        #pragma unroll
        for (int i = 0; i < 4; i++){
            int u = i*256 + tid; int o = u >> 3, seg = u & 7;
            cpa16(bu + (o*APAD + seg*4)*4, wn + o*CM + seg*4);
        }
    };
    auto fillA = [&](int it, int buf){
        int n = it >> 2, c0 = (it & 3) << 5;
        const float* yb = g_y + c0 + lane;
        uint32_t* Ad = AsB[buf];
        #pragma unroll 4
        for (int r = 0; r < 16; r++){
            int px = warp*16 + r;
            int pr = px*9 + n;
            int4   id = sIdx[pr];
            float4 wt = sWt[pr];
            float v = wt.x*yb[id.x] + wt.y*yb[id.y] + wt.z*yb[id.z] + wt.w*yb[id.w];
            Ad[px*APAD + lane] = f2tf32(v);
        }
    };

    // prologue: chunk 0 into buffer 0
    fillB(0, 0); CPA_COMMIT();
    fillA(0, 0);
    CPA_WAIT0();
    __syncthreads();

    int cur = 0;
    for (int it = 0; it < 36; it++){
        int nb = cur ^ 1;
        if (it < 35){ fillB(it+1, nb); CPA_COMMIT(); }   // async under mma
        mma_tile_128(AsB[cur], BsB[cur], wm, wnn, gid, tig, acc);
        if (it < 35) fillA(it+1, nb);                     // covered by other warps' mma
        CPA_WAIT0();
        __syncthreads();
        cur = nb;
    }

    // epilogue: bn2 + silu, NHWC float2 stores
    #pragma unroll
    for (int mt = 0; mt < 2; mt++){
        int r0 = wm*32 + mt*16 + gid;
        float* z0 = g_z + (size_t)(b_*HW + p0 + r0)*CM;
        float* z1 = z0 + 8*CM;
        #pragma unroll
        for (int nt = 0; nt < 8; nt++){
            int cb = wnn*64 + nt*8 + 2*tig;
            float s0 = sS[cb], s1 = sS[cb+1], t0 = sT[cb], t1 = sT[cb+1];
            float2 v0, v1;
            v0.x = silu_f(acc[mt][nt][0]*s0 + t0);
            v0.y = silu_f(acc[mt][nt][1]*s1 + t1);
            v1.x = silu_f(acc[mt][nt][2]*s0 + t0);
            v1.y = silu_f(acc[mt][nt][3]*s1 + t1);
            *(float2*)(z0 + cb) = v0;
            *(float2*)(z1 + cb) = v1;
        }
    }
}

// ---------------- K4: conv1x1(128->256) + bn3 + silu + residual -> out (NCHW), tf32 mma ----------------
__global__ void __launch_bounds__(256, 2) k4_mma(const float* __restrict__ x, float* __restrict__ out,
        const float* __restrict__ w3,
        const float* __restrict__ g3, const float* __restrict__ b3,
        const float* __restrict__ m3, const float* __restrict__ v3){
    __shared__ __align__(16) uint32_t As[128*APAD];
    __shared__ __align__(16) uint32_t Bs[128*APAD];
    __shared__ float sS[128], sT[128];
    int blk = blockIdx.x;
    int b_ = blk / 50;
    int p0 = (blk % 50) * 128;
    int o0g = blockIdx.y * 128;
    int tid = threadIdx.x, warp = tid >> 5, lane = tid & 31;
    int wm = warp & 3, wnn = warp >> 2, gid = lane >> 2, tig = lane & 3;
    if (tid < 128){
        int o = o0g + tid;
        float s = g3[o] * rsqrtf(v3[o] + EPSF);
        sS[tid] = s;
        sT[tid] = b3[o] - m3[o]*s;
    }
    float acc[2][8][4] = {};
    const float* zt = g_z + (size_t)(b_*HW + p0)*CM;
    const float* wb = w3 + (size_t)o0g*CM;
    uint32_t asu = s2u(As), bsu = s2u(Bs);
    for (int kc = 0; kc < 4; kc++){
        int k0 = kc*32;
        #pragma unroll
        for (int i = 0; i < 4; i++){
            int u = i*256 + tid; int r = u >> 3, seg = u & 7;
            cpa16(asu + (r*APAD + seg*4)*4, zt + (size_t)r*CM + k0 + seg*4);
            cpa16(bsu + (r*APAD + seg*4)*4, wb + r*CM + k0 + seg*4);
        }
        CPA_COMMIT();
        CPA_WAIT0();
        __syncthreads();
        mma_tile_128(As, Bs, wm, wnn, gid, tig, acc);
        __syncthreads();
    }
    #pragma unroll
    for (int mt = 0; mt < 2; mt++){
        int pg0 = p0 + wm*32 + mt*16 + gid;
        #pragma unroll
        for (int nt = 0; nt < 8; nt++){
            int o = o0g + wnn*64 + nt*8 + 2*tig;
            float s0 = sS[o - o0g], s1 = sS[o - o0g + 1];
            float t0 = sT[o - o0g], t1 = sT[o - o0g + 1];
            size_t i00 = ((size_t)b_*C2 + o)*HW + pg0;
            size_t i01 = i00 + HW;
            out[i00]     = x[i00]     + silu_f(acc[mt][nt][0]*s0 + t0);
            out[i01]     = x[i01]     + silu_f(acc[mt][nt][1]*s1 + t1);
            out[i00 + 8] = x[i00 + 8] + silu_f(acc[mt][nt][2]*s0 + t0);
            out[i01 + 8] = x[i01 + 8] + silu_f(acc[mt][nt][3]*s1 + t1);
        }
    }
}

// ---------------- launch ----------------
extern "C" void kernel_launch(void* const* d_in, const int* in_sizes, int n_in,
                              void* d_out, int out_size){
    const float* x     = (const float*)d_in[0];
    const float* cv1_w = (const float*)d_in[1];
    const float* bn1g  = (const float*)d_in[2];
    const float* bn1b  = (const float*)d_in[3];
    const float* bn1m  = (const float*)d_in[4];
    const float* bn1v  = (const float*)d_in[5];
    const float* off_w = (const float*)d_in[6];
    const float* off_b = (const float*)d_in[7];
    const float* dcn_w = (const float*)d_in[8];
    const float* dcn_b = (const float*)d_in[9];
    const float* bn2g  = (const float*)d_in[10];
    const float* bn2b  = (const float*)d_in[11];
    const float* bn2m  = (const float*)d_in[12];
    const float* bn2v  = (const float*)d_in[13];
    const float* cv3_w = (const float*)d_in[14];
    const float* bn3g  = (const float*)d_in[15];
    const float* bn3b  = (const float*)d_in[16];
    const float* bn3m  = (const float*)d_in[17];
    const float* bn3v  = (const float*)d_in[18];
    float* out = (float*)d_out;

    prep_w<<<(N9*CM*CM + 255)/256, 256>>>(off_w, dcn_w);
    k1_mma<<<BSZ*50, 256>>>(x, cv1_w, bn1g, bn1b, bn1m, bn1v);
    k2_mma<<<BSZ*50, 256>>>(off_b);

    int smem_bytes = K3_SMEM_F * 4;  // 111616 B
    cudaFuncSetAttribute(k3_deform_mma, cudaFuncAttributeMaxDynamicSharedMemorySize, smem_bytes);
    k3_deform_mma<<<BSZ*50, 256, smem_bytes>>>(dcn_b, bn2g, bn2b, bn2m, bn2v);

    k4_mma<<<dim3(BSZ*50, 2), 256>>>(x, out, cv3_w, bn3g, bn3b, bn3m, bn3v);
}

// round 8
// speedup vs baseline: 2.1268x; 1.0635x over previous
#include <cuda_runtime.h>
#include <math.h>
#include <stdint.h>

#define BSZ   8
#define C1    256
#define C2    256
#define CM    128
#define Hh    80
#define Ww    80
#define HW    6400
#define N9    9
#define KCN   1152      // CM * 9
#define NOFF  27
#define EPSF  1e-5f

// ---------------- scratch (device globals; no runtime alloc) ----------------
__device__ __align__(16) float g_y   [BSZ*HW*CM];     // NHWC  y = silu(bn1(conv1))
__device__ __align__(16) float g_pred[BSZ*HW*NOFF];   // per-pixel [27]
__device__ __align__(16) float g_z   [BSZ*HW*CM];     // NHWC  deform+bn2+silu
__device__ __align__(16) float g_w2o [N9*32*CM];      // [n][o pad 32][c]
__device__ __align__(16) float g_wd2 [N9*CM*CM];      // [n][o][c]

__device__ __forceinline__ float silu_f(float v){ return v / (1.f + __expf(-v)); }
__device__ __forceinline__ uint32_t f2tf32(float v){
    uint32_t t; asm("cvt.rna.tf32.f32 %0, %1;" : "=r"(t) : "f"(v));
    return t;
}
__device__ __forceinline__ uint32_t s2u(const void* p){
    return (uint32_t)__cvta_generic_to_shared(p);
}
__device__ __forceinline__ void cpa16(uint32_t s, const void* g){
    asm volatile("cp.async.cg.shared.global [%0], [%1], 16;" :: "r"(s), "l"(g));
}
#define CPA_COMMIT() asm volatile("cp.async.commit_group;" ::: "memory")
#define CPA_WAIT0()  asm volatile("cp.async.wait_group 0;" ::: "memory")

#define APAD 36
#define MMA_STEP(accq, a0,a1,a2,a3, b0,b1) \
    asm volatile("mma.sync.aligned.m16n8k8.row.col.f32.tf32.tf32.f32 " \
        "{%0,%1,%2,%3}, {%4,%5,%6,%7}, {%8,%9}, {%0,%1,%2,%3};" \
        : "+f"((accq)[0]), "+f"((accq)[1]), "+f"((accq)[2]), "+f"((accq)[3]) \
        : "r"(a0), "r"(a1), "r"(a2), "r"(a3), "r"(b0), "r"(b1))

// generic 128x128 warp-tiled mma on As[128][APAD], Bs[128][APAD] (tf32 bits)
__device__ __forceinline__ void mma_tile_128(const uint32_t* As, const uint32_t* Bs,
                                             int wm, int wnn, int gid, int tig,
                                             float acc[2][8][4]){
    const uint32_t* Ab = As + (wm*32 + gid)*APAD;
    const uint32_t* Bb = Bs + (wnn*64 + gid)*APAD;
    #pragma unroll
    for (int kk = 0; kk < 4; kk++){
        int kb = kk*8 + tig;
        uint32_t a[2][4];
        #pragma unroll
        for (int mt = 0; mt < 2; mt++){
            a[mt][0] = Ab[(mt*16)*APAD + kb];
            a[mt][1] = Ab[(mt*16+8)*APAD + kb];
            a[mt][2] = Ab[(mt*16)*APAD + kb + 4];
            a[mt][3] = Ab[(mt*16+8)*APAD + kb + 4];
        }
        #pragma unroll
        for (int nt = 0; nt < 8; nt++){
            uint32_t b0 = Bb[(nt*8)*APAD + kb];
            uint32_t b1 = Bb[(nt*8)*APAD + kb + 4];
            #pragma unroll
            for (int mt = 0; mt < 2; mt++)
                MMA_STEP(acc[mt][nt], a[mt][0],a[mt][1],a[mt][2],a[mt][3], b0,b1);
        }
    }
}

// ---------------- K0: weight reshapes ----------------
__global__ void prep_w(const float* __restrict__ w2, const float* __restrict__ wd){
    int i = blockIdx.x*blockDim.x + threadIdx.x;
    if (i < N9*32*CM){
        int n = i/(32*CM); int o = (i/CM) & 31; int c = i % CM;
        g_w2o[i] = (o < NOFF) ? w2[o*KCN + c*9 + n] : 0.f;
    }
    if (i < N9*CM*CM){
        int n = i/(CM*CM); int rest = i%(CM*CM); int o = rest/CM, c = rest%CM;
        g_wd2[i] = wd[o*KCN + c*9 + n];
    }
}

// ---------------- K1: conv1x1(256->128) + bn1 + silu -> g_y (NHWC), tf32 mma ----------------
__global__ void __launch_bounds__(256, 2) k1_mma(const float* __restrict__ x,
        const float* __restrict__ w1,
        const float* __restrict__ g1, const float* __restrict__ b1,
        const float* __restrict__ m1, const float* __restrict__ v1){
    __shared__ __align__(16) uint32_t As[128*APAD];
    __shared__ __align__(16) uint32_t Bs[128*APAD];
    __shared__ float sS[128], sT[128];
    int blk = blockIdx.x;
    int b_ = blk / 50;
    int p0 = (blk % 50) * 128;
    int tid = threadIdx.x, warp = tid >> 5, lane = tid & 31;
    int wm = warp & 3, wnn = warp >> 2, gid = lane >> 2, tig = lane & 3;
    if (tid < 128){
        float s = g1[tid] * rsqrtf(v1[tid] + EPSF);
        sS[tid] = s;
        sT[tid] = b1[tid] - m1[tid]*s;
    }
    float acc[2][8][4] = {};
    const float* xb = x + (size_t)b_*C1*HW + p0;
    uint32_t bsu = s2u(Bs);
    for (int kc = 0; kc < 8; kc++){
        int k0 = kc*32;
        // B: cp.async 16B, raw fp32 (HW tf32-truncates)
        #pragma unroll
        for (int i = 0; i < 4; i++){
            int u = i*256 + tid; int r = u >> 3, seg = u & 7;
            cpa16(bsu + (r*APAD + seg*4)*4, w1 + r*C1 + k0 + seg*4);
        }
        CPA_COMMIT();
        // A: NCHW transpose load, lane -> pixel (coalesced)
        #pragma unroll
        for (int i = 0; i < 16; i++){
            int e = i*256 + tid; int kk = e >> 7, px = e & 127;
            As[px*APAD + kk] = f2tf32(xb[(size_t)(k0+kk)*HW + px]);
        }
        CPA_WAIT0();
        __syncthreads();
        mma_tile_128(As, Bs, wm, wnn, gid, tig, acc);
        __syncthreads();
    }
    #pragma unroll
    for (int mt = 0; mt < 2; mt++){
        int r0 = wm*32 + mt*16 + gid;
        float* z0 = g_y + (size_t)(b_*HW + p0 + r0)*CM;
        float* z1 = z0 + 8*CM;
        #pragma unroll
        for (int nt = 0; nt < 8; nt++){
            int cb = wnn*64 + nt*8 + 2*tig;
            float s0 = sS[cb], s1 = sS[cb+1], t0 = sT[cb], t1 = sT[cb+1];
            float2 v0, v1;
            v0.x = silu_f(acc[mt][nt][0]*s0 + t0);
            v0.y = silu_f(acc[mt][nt][1]*s1 + t1);
            v1.x = silu_f(acc[mt][nt][2]*s0 + t0);
            v1.y = silu_f(acc[mt][nt][3]*s1 + t1);
            *(float2*)(z0 + cb) = v0;
            *(float2*)(z1 + cb) = v1;
        }
    }
}

// ---------------- K2: conv3x3(128->27) via tf32 mma (implicit im2col) -> g_pred ----------------
__global__ void __launch_bounds__(256, 4) k2_mma(const float* __restrict__ offb){
    __shared__ __align__(16) uint32_t As[128*APAD];
    __shared__ __align__(16) uint32_t Bs[32*APAD];
    __shared__ float sB[32];
    int blk = blockIdx.x;
    int b_ = blk / 50;
    int p0 = (blk % 50) * 128;
    int tid = threadIdx.x, warp = tid >> 5, lane = tid & 31;
    int gid = lane >> 2, tig = lane & 3;
    int sub = lane >> 3, grp = lane & 7;
    if (tid < 32) sB[tid] = (tid < NOFF) ? offb[tid] : 0.f;

    float acc[4][4] = {};
    for (int it = 0; it < 36; it++){
        int n  = it >> 2;
        int c0 = (it & 3) << 5;
        int dy = n/3 - 1, dx = n%3 - 1;
        #pragma unroll
        for (int i = 0; i < 4; i++){
            int e = i*256 + tid; int o = e >> 5, k = e & 31;
            Bs[o*APAD + k] = f2tf32(g_w2o[(n*32 + o)*CM + c0 + k]);
        }
        // A: im2col float4 fill (4 rows x 8 groups per warp-pass)
        #pragma unroll
        for (int p = 0; p < 4; p++){
            int px = warp*16 + p*4 + sub;
            int pg = p0 + px, h = pg / Ww, w = pg % Ww;
            int sy = h + dy, sx = w + dx;
            bool ok = (sy >= 0) & (sy < Hh) & (sx >= 0) & (sx < Ww);
            float4 v = make_float4(0.f, 0.f, 0.f, 0.f);
            if (ok)
                v = *(const float4*)(g_y + (size_t)(b_*HW + sy*Ww + sx)*CM + c0 + grp*4);
            uint4 t;
            t.x = f2tf32(v.x); t.y = f2tf32(v.y); t.z = f2tf32(v.z); t.w = f2tf32(v.w);
            *(uint4*)(As + px*APAD + grp*4) = t;
        }
        __syncthreads();
        const uint32_t* Ab = As + (warp*16 + gid)*APAD;
        const uint32_t* Bb = Bs + gid*APAD;
        #pragma unroll
        for (int kk = 0; kk < 4; kk++){
            int kb = kk*8 + tig;
            uint32_t a0 = Ab[kb], a1 = Ab[8*APAD + kb];
            uint32_t a2 = Ab[kb + 4], a3 = Ab[8*APAD + kb + 4];
            #pragma unroll
            for (int nt = 0; nt < 4; nt++){
                uint32_t b0 = Bb[(nt*8)*APAD + kb];
                uint32_t b1 = Bb[(nt*8)*APAD + kb + 4];
                MMA_STEP(acc[nt], a0,a1,a2,a3, b0,b1);
            }
        }
        __syncthreads();
    }
    #pragma unroll
    for (int half = 0; half < 2; half++){
        int px = warp*16 + gid + half*8;
        float* pp = g_pred + (size_t)(b_*HW + p0 + px)*NOFF;
        #pragma unroll
        for (int nt = 0; nt < 4; nt++){
            int c = nt*8 + 2*tig;
            float v0 = acc[nt][half*2 + 0] + sB[c];
            float v1 = acc[nt][half*2 + 1] + sB[c+1];
            if (c >= 18)   v0 = 1.f/(1.f + __expf(-v0));
            if (c+1 >= 18) v1 = 1.f/(1.f + __expf(-v1));
            if (c < NOFF)   pp[c]   = v0;
            if (c+1 < NOFF) pp[c+1] = v1;
        }
    }
}

// ---------------- K3: deform conv via mma.sync tf32, double-buffered, float4 gather ----------------
#define K3_F_AS0  0
#define K3_F_AS1  (128*APAD)
#define K3_F_BS0  (2*128*APAD)
#define K3_F_BS1  (3*128*APAD)
#define K3_F_IDX  (4*128*APAD)
#define K3_F_WT   (K3_F_IDX + 4608)
#define K3_F_S    (K3_F_WT + 4608)
#define K3_F_T    (K3_F_S + 128)
#define K3_SMEM_F (K3_F_T + 128)

__global__ void __launch_bounds__(256, 2) k3_deform_mma(const float* __restrict__ dcnb,
        const float* __restrict__ g2, const float* __restrict__ b2,
        const float* __restrict__ m2, const float* __restrict__ v2){
    extern __shared__ float sm[];
    uint32_t* AsB[2] = { (uint32_t*)(sm + K3_F_AS0), (uint32_t*)(sm + K3_F_AS1) };
    uint32_t* BsB[2] = { (uint32_t*)(sm + K3_F_BS0), (uint32_t*)(sm + K3_F_BS1) };
    int4*   sIdx = (int4*)(sm + K3_F_IDX);
    float4* sWt  = (float4*)(sm + K3_F_WT);
    float* sS = sm + K3_F_S;
    float* sT = sm + K3_F_T;

    int blk = blockIdx.x;
    int b_ = blk / 50;
    int p0 = (blk % 50) * 128;
    int tid = threadIdx.x, warp = tid >> 5, lane = tid & 31;

    // setup: precompute bilinear corner indices + mask/validity-folded weights
    for (int pr = tid; pr < 128*9; pr += 256){
        int p = pr / 9, nn = pr % 9;
        int pg = p0 + p, h = pg / Ww, w = pg % Ww;
        size_t pb = (size_t)(b_*HW + pg) * NOFF;
        float py = (float)(h - 1 + nn/3) + g_pred[pb + 2*nn];
        float qx = (float)(w - 1 + nn%3) + g_pred[pb + 2*nn + 1];
        float mk = g_pred[pb + 18 + nn];
        float y0f = floorf(py), x0f = floorf(qx);
        float wy = py - y0f, wx = qx - x0f;
        int iy0 = (int)y0f, ix0 = (int)x0f, iy1 = iy0 + 1, ix1 = ix0 + 1;
        float vy0 = (iy0 >= 0 && iy0 < Hh) ? 1.f : 0.f;
        float vy1 = (iy1 >= 0 && iy1 < Hh) ? 1.f : 0.f;
        float vx0 = (ix0 >= 0 && ix0 < Ww) ? 1.f : 0.f;
        float vx1 = (ix1 >= 0 && ix1 < Ww) ? 1.f : 0.f;
        int cy0 = min(max(iy0,0),Hh-1), cy1 = min(max(iy1,0),Hh-1);
        int cx0 = min(max(ix0,0),Ww-1), cx1 = min(max(ix1,0),Ww-1);
        int base = b_*HW;
        int4 id;
        id.x = (base + cy0*Ww + cx0)*CM;
        id.y = (base + cy0*Ww + cx1)*CM;
        id.z = (base + cy1*Ww + cx0)*CM;
        id.w = (base + cy1*Ww + cx1)*CM;
        float4 wt;
        wt.x = (1.f-wy)*(1.f-wx)*mk*vy0*vx0;
        wt.y = (1.f-wy)*wx      *mk*vy0*vx1;
        wt.z = wy*(1.f-wx)      *mk*vy1*vx0;
        wt.w = wy*wx            *mk*vy1*vx1;
        sIdx[pr] = id;
        sWt[pr]  = wt;
    }
    if (tid < 128){
        float s = g2[tid] * rsqrtf(v2[tid] + EPSF);
        sS[tid] = s;
        sT[tid] = dcnb[tid]*s + b2[tid] - m2[tid]*s;
    }
    __syncthreads();

    int wm = warp & 3, wnn = warp >> 2, gid = lane >> 2, tig = lane & 3;
    int sub = lane >> 3, grp = lane & 7;
    float acc[2][8][4] = {};

    auto fillB = [&](int it, int buf){
        int n = it >> 2, c0 = (it & 3) << 5;
        const float* wn = g_wd2 + n*(CM*CM) + c0;
        uint32_t bu = s2u(BsB[buf]);
        #pragma unroll
        for (int i = 0; i < 4; i++){
            int u = i*256 + tid; int o = u >> 3, seg = u & 7;
            cpa16(bu + (o*APAD + seg*4)*4, wn + o*CM + seg*4);
        }
    };
    // float4 gather: 4 rows x 8 channel-groups per warp-pass, 4 passes
    auto fillA = [&](int it, int buf){
        int n = it >> 2, c0 = (it & 3) << 5;
        const float* yb = g_y + c0 + grp*4;
        uint32_t* Ad = AsB[buf];
        #pragma unroll
        for (int p = 0; p < 4; p++){
            int px = warp*16 + p*4 + sub;
            int pr = px*9 + n;
            int4   id = sIdx[pr];
            float4 wt = sWt[pr];
            float4 c00 = *(const float4*)(yb + id.x);
            float4 c01 = *(const float4*)(yb + id.y);
            float4 c10 = *(const float4*)(yb + id.z);
            float4 c11 = *(const float4*)(yb + id.w);
            float4 v;
            v.x = wt.x*c00.x + wt.y*c01.x + wt.z*c10.x + wt.w*c11.x;
            v.y = wt.x*c00.y + wt.y*c01.y + wt.z*c10.y + wt.w*c11.y;
            v.z = wt.x*c00.z + wt.y*c01.z + wt.z*c10.z + wt.w*c11.z;
            v.w = wt.x*c00.w + wt.y*c01.w + wt.z*c10.w + wt.w*c11.w;
            uint4 t;
            t.x = f2tf32(v.x); t.y = f2tf32(v.y); t.z = f2tf32(v.z); t.w = f2tf32(v.w);
            *(uint4*)(Ad + px*APAD + grp*4) = t;
        }
    };

    // prologue: chunk 0 into buffer 0
    fillB(0, 0); CPA_COMMIT();
    fillA(0, 0);
    CPA_WAIT0();
    __syncthreads();

    int cur = 0;
    for (int it = 0; it < 36; it++){
        int nb = cur ^ 1;
        if (it < 35){ fillB(it+1, nb); CPA_COMMIT(); }
        mma_tile_128(AsB[cur], BsB[cur], wm, wnn, gid, tig, acc);
        if (it < 35) fillA(it+1, nb);
        CPA_WAIT0();
        __syncthreads();
        cur = nb;
    }

    // epilogue: bn2 + silu, NHWC float2 stores
    #pragma unroll
    for (int mt = 0; mt < 2; mt++){
        int r0 = wm*32 + mt*16 + gid;
        float* z0 = g_z + (size_t)(b_*HW + p0 + r0)*CM;
        float* z1 = z0 + 8*CM;
        #pragma unroll
        for (int nt = 0; nt < 8; nt++){
            int cb = wnn*64 + nt*8 + 2*tig;
            float s0 = sS[cb], s1 = sS[cb+1], t0 = sT[cb], t1 = sT[cb+1];
            float2 v0, v1;
            v0.x = silu_f(acc[mt][nt][0]*s0 + t0);
            v0.y = silu_f(acc[mt][nt][1]*s1 + t1);
            v1.x = silu_f(acc[mt][nt][2]*s0 + t0);
            v1.y = silu_f(acc[mt][nt][3]*s1 + t1);
            *(float2*)(z0 + cb) = v0;
            *(float2*)(z1 + cb) = v1;
        }
    }
}

// ---------------- K4: conv1x1(128->256) + bn3 + silu + residual -> out (NCHW), tf32 mma ----------------
__global__ void __launch_bounds__(256, 2) k4_mma(const float* __restrict__ x, float* __restrict__ out,
        const float* __restrict__ w3,
        const float* __restrict__ g3, const float* __restrict__ b3,
        const float* __restrict__ m3, const float* __restrict__ v3){
    __shared__ __align__(16) uint32_t As[128*APAD];
    __shared__ __align__(16) uint32_t Bs[128*APAD];
    __shared__ float sS[128], sT[128];
    int blk = blockIdx.x;
    int b_ = blk / 50;
    int p0 = (blk % 50) * 128;
    int o0g = blockIdx.y * 128;
    int tid = threadIdx.x, warp = tid >> 5, lane = tid & 31;
    int wm = warp & 3, wnn = warp >> 2, gid = lane >> 2, tig = lane & 3;
    if (tid < 128){
        int o = o0g + tid;
        float s = g3[o] * rsqrtf(v3[o] + EPSF);
        sS[tid] = s;
        sT[tid] = b3[o] - m3[o]*s;
    }
    float acc[2][8][4] = {};
    const float* zt = g_z + (size_t)(b_*HW + p0)*CM;
    const float* wb = w3 + (size_t)o0g*CM;
    uint32_t asu = s2u(As), bsu = s2u(Bs);
    for (int kc = 0; kc < 4; kc++){
        int k0 = kc*32;
        #pragma unroll
        for (int i = 0; i < 4; i++){
            int u = i*256 + tid; int r = u >> 3, seg = u & 7;
            cpa16(asu + (r*APAD + seg*4)*4, zt + (size_t)r*CM + k0 + seg*4);
            cpa16(bsu + (r*APAD + seg*4)*4, wb + r*CM + k0 + seg*4);
        }
        CPA_COMMIT();
        CPA_WAIT0();
        __syncthreads();
        mma_tile_128(As, Bs, wm, wnn, gid, tig, acc);
        __syncthreads();
    }
    #pragma unroll
    for (int mt = 0; mt < 2; mt++){
        int pg0 = p0 + wm*32 + mt*16 + gid;
        #pragma unroll
        for (int nt = 0; nt < 8; nt++){
            int o = o0g + wnn*64 + nt*8 + 2*tig;
            float s0 = sS[o - o0g], s1 = sS[o - o0g + 1];
            float t0 = sT[o - o0g], t1 = sT[o - o0g + 1];
            size_t i00 = ((size_t)b_*C2 + o)*HW + pg0;
            size_t i01 = i00 + HW;
            out[i00]     = x[i00]     + silu_f(acc[mt][nt][0]*s0 + t0);
            out[i01]     = x[i01]     + silu_f(acc[mt][nt][1]*s1 + t1);
            out[i00 + 8] = x[i00 + 8] + silu_f(acc[mt][nt][2]*s0 + t0);
            out[i01 + 8] = x[i01 + 8] + silu_f(acc[mt][nt][3]*s1 + t1);
        }
    }
}

// ---------------- launch ----------------
extern "C" void kernel_launch(void* const* d_in, const int* in_sizes, int n_in,
                              void* d_out, int out_size){
    const float* x     = (const float*)d_in[0];
    const float* cv1_w = (const float*)d_in[1];
    const float* bn1g  = (const float*)d_in[2];
    const float* bn1b  = (const float*)d_in[3];
    const float* bn1m  = (const float*)d_in[4];
    const float* bn1v  = (const float*)d_in[5];
    const float* off_w = (const float*)d_in[6];
    const float* off_b = (const float*)d_in[7];
    const float* dcn_w = (const float*)d_in[8];
    const float* dcn_b = (const float*)d_in[9];
    const float* bn2g  = (const float*)d_in[10];
    const float* bn2b  = (const float*)d_in[11];
    const float* bn2m  = (const float*)d_in[12];
    const float* bn2v  = (const float*)d_in[13];
    const float* cv3_w = (const float*)d_in[14];
    const float* bn3g  = (const float*)d_in[15];
    const float* bn3b  = (const float*)d_in[16];
    const float* bn3m  = (const float*)d_in[17];
    const float* bn3v  = (const float*)d_in[18];
    float* out = (float*)d_out;

    prep_w<<<(N9*CM*CM + 255)/256, 256>>>(off_w, dcn_w);
    k1_mma<<<BSZ*50, 256>>>(x, cv1_w, bn1g, bn1b, bn1m, bn1v);
    k2_mma<<<BSZ*50, 256>>>(off_b);

    int smem_bytes = K3_SMEM_F * 4;  // 111616 B
    cudaFuncSetAttribute(k3_deform_mma, cudaFuncAttributeMaxDynamicSharedMemorySize, smem_bytes);
    k3_deform_mma<<<BSZ*50, 256, smem_bytes>>>(dcn_b, bn2g, bn2b, bn2m, bn2v);

    k4_mma<<<dim3(BSZ*50, 2), 256>>>(x, out, cv3_w, bn3g, bn3b, bn3m, bn3v);
}

// round 9
// speedup vs baseline: 4.6985x; 2.2092x over previous
#include <cuda_runtime.h>
#include <cuda_fp16.h>
#include <math.h>
#include <stdint.h>

#define BSZ   8
#define C1    256
#define C2    256
#define CM    128
#define Hh    80
#define Ww    80
#define HW    6400
#define N9    9
#define KCN   1152      // CM * 9
#define NOFF  27
#define EPSF  1e-5f

// ---------------- scratch (device globals; no runtime alloc) ----------------
__device__ __align__(16) __half g_yh  [BSZ*HW*CM];    // NHWC y (fp16)
__device__ __align__(16) __half g_zh  [BSZ*HW*CM];    // NHWC z (fp16)
__device__ __align__(16) float  g_pred[BSZ*HW*NOFF];  // per-pixel [27] fp32
__device__ __align__(16) __half g_w1h [CM*C1];        // [o][k]
__device__ __align__(16) __half g_w2h [N9*32*CM];     // [n][o pad 32][c]
__device__ __align__(16) __half g_wdh [N9*CM*CM];     // [n][o][c]
__device__ __align__(16) __half g_w3h [C2*CM];        // [o][k]

__device__ __forceinline__ float silu_f(float v){ return v / (1.f + __expf(-v)); }
__device__ __forceinline__ uint32_t s2u(const void* p){
    return (uint32_t)__cvta_generic_to_shared(p);
}
__device__ __forceinline__ void cpa16(uint32_t s, const void* g){
    asm volatile("cp.async.cg.shared.global [%0], [%1], 16;" :: "r"(s), "l"(g));
}
#define CPA_COMMIT() asm volatile("cp.async.commit_group;" ::: "memory")
#define CPA_WAIT0()  asm volatile("cp.async.wait_group 0;" ::: "memory")

// row pitch in u32 (16 u32 = 32 halves data + pad 4) -> 80B rows, uint4-aligned
#define HPAD 20

#define MMA_F16(accq, a0,a1,a2,a3, b0,b1) \
    asm volatile("mma.sync.aligned.m16n8k16.row.col.f32.f16.f16.f32 " \
        "{%0,%1,%2,%3}, {%4,%5,%6,%7}, {%8,%9}, {%0,%1,%2,%3};" \
        : "+f"((accq)[0]), "+f"((accq)[1]), "+f"((accq)[2]), "+f"((accq)[3]) \
        : "r"(a0), "r"(a1), "r"(a2), "r"(a3), "r"(b0), "r"(b1))

// 128x128 warp-tiled fp16 mma on As[128][HPAD], Bs[128][HPAD] (k-chunk = 32)
__device__ __forceinline__ void mma_f16_128(const uint32_t* As, const uint32_t* Bs,
                                            int wm, int wnn, int gid, int tig,
                                            float acc[2][8][4]){
    const uint32_t* Ab = As + (wm*32 + gid)*HPAD;
    const uint32_t* Bb = Bs + (wnn*64 + gid)*HPAD;
    #pragma unroll
    for (int kk = 0; kk < 2; kk++){
        int kb = kk*8 + tig;
        uint32_t a[2][4];
        #pragma unroll
        for (int mt = 0; mt < 2; mt++){
            a[mt][0] = Ab[(mt*16)*HPAD + kb];
            a[mt][1] = Ab[(mt*16+8)*HPAD + kb];
            a[mt][2] = Ab[(mt*16)*HPAD + kb + 4];
            a[mt][3] = Ab[(mt*16+8)*HPAD + kb + 4];
        }
        #pragma unroll
        for (int nt = 0; nt < 8; nt++){
            uint32_t b0 = Bb[(nt*8)*HPAD + kb];
            uint32_t b1 = Bb[(nt*8)*HPAD + kb + 4];
            #pragma unroll
            for (int mt = 0; mt < 2; mt++)
                MMA_F16(acc[mt][nt], a[mt][0],a[mt][1],a[mt][2],a[mt][3], b0,b1);
        }
    }
}

// ---------------- K0: weight conversions/reshapes to fp16 ----------------
__global__ void prep_w(const float* __restrict__ w1, const float* __restrict__ w2,
                       const float* __restrict__ wd, const float* __restrict__ w3){
    int i = blockIdx.x*blockDim.x + threadIdx.x;
    if (i < CM*C1)  g_w1h[i] = __float2half(w1[i]);
    if (i < C2*CM)  g_w3h[i] = __float2half(w3[i]);
    if (i < N9*32*CM){
        int n = i/(32*CM); int o = (i/CM) & 31; int c = i % CM;
        g_w2h[i] = (o < NOFF) ? __float2half(w2[o*KCN + c*9 + n]) : __float2half(0.f);
    }
    if (i < N9*CM*CM){
        int n = i/(CM*CM); int rest = i%(CM*CM); int o = rest/CM, c = rest%CM;
        g_wdh[i] = __float2half(wd[o*KCN + c*9 + n]);
    }
}

// ---------------- K1: conv1x1(256->128) + bn1 + silu -> g_yh (NHWC fp16) ----------------
__global__ void __launch_bounds__(256, 2) k1_mma(const float* __restrict__ x,
        const float* __restrict__ g1, const float* __restrict__ b1,
        const float* __restrict__ m1, const float* __restrict__ v1){
    __shared__ __align__(16) uint32_t As[128*HPAD];
    __shared__ __align__(16) uint32_t Bs[128*HPAD];
    __shared__ float sS[128], sT[128];
    int blk = blockIdx.x;
    int b_ = blk / 50;
    int p0 = (blk % 50) * 128;
    int tid = threadIdx.x, warp = tid >> 5, lane = tid & 31;
    int wm = warp & 3, wnn = warp >> 2, gid = lane >> 2, tig = lane & 3;
    if (tid < 128){
        float s = g1[tid] * rsqrtf(v1[tid] + EPSF);
        sS[tid] = s;
        sT[tid] = b1[tid] - m1[tid]*s;
    }
    float acc[2][8][4] = {};
    const float* xb = x + (size_t)b_*C1*HW + p0;
    uint32_t bsu = s2u(Bs);
    for (int kc = 0; kc < 8; kc++){
        int k0 = kc*32;
        #pragma unroll
        for (int i = 0; i < 2; i++){
            int u = i*256 + tid; int o = u >> 2, seg = u & 3;
            cpa16(bsu + (o*HPAD + seg*4)*4, g_w1h + o*C1 + k0 + seg*8);
        }
        CPA_COMMIT();
        // A: NCHW load (coalesced over px), pack half2 along k
        #pragma unroll
        for (int i = 0; i < 8; i++){
            int e = i*256 + tid; int j = e >> 7, px = e & 127;
            float f0 = xb[(size_t)(k0 + 2*j)*HW + px];
            float f1 = xb[(size_t)(k0 + 2*j + 1)*HW + px];
            __half2 hh = __float22half2_rn(make_float2(f0, f1));
            As[px*HPAD + j] = *(uint32_t*)&hh;
        }
        CPA_WAIT0();
        __syncthreads();
        mma_f16_128(As, Bs, wm, wnn, gid, tig, acc);
        __syncthreads();
    }
    #pragma unroll
    for (int mt = 0; mt < 2; mt++){
        int r0 = wm*32 + mt*16 + gid;
        __half2* z0 = (__half2*)(g_yh + (size_t)(b_*HW + p0 + r0)*CM);
        __half2* z1 = (__half2*)(g_yh + (size_t)(b_*HW + p0 + r0 + 8)*CM);
        #pragma unroll
        for (int nt = 0; nt < 8; nt++){
            int cb = wnn*64 + nt*8 + 2*tig;
            float s0 = sS[cb], s1 = sS[cb+1], t0 = sT[cb], t1 = sT[cb+1];
            z0[cb>>1] = __float22half2_rn(make_float2(
                silu_f(acc[mt][nt][0]*s0 + t0), silu_f(acc[mt][nt][1]*s1 + t1)));
            z1[cb>>1] = __float22half2_rn(make_float2(
                silu_f(acc[mt][nt][2]*s0 + t0), silu_f(acc[mt][nt][3]*s1 + t1)));
        }
    }
}

// ---------------- K2: conv3x3(128->27) via fp16 mma (implicit im2col) -> g_pred ----------------
__global__ void __launch_bounds__(256, 4) k2_mma(const float* __restrict__ offb){
    __shared__ __align__(16) uint32_t As[128*HPAD];
    __shared__ __align__(16) uint32_t Bs[32*HPAD];
    __shared__ float sB[32];
    int blk = blockIdx.x;
    int b_ = blk / 50;
    int p0 = (blk % 50) * 128;
    int tid = threadIdx.x, warp = tid >> 5, lane = tid & 31;
    int gid = lane >> 2, tig = lane & 3;
    int sub = lane >> 2, grp = lane & 3;     // 8 px x 4 channel-groups (8ch each)
    if (tid < 32) sB[tid] = (tid < NOFF) ? offb[tid] : 0.f;
    uint32_t bsu = s2u(Bs);

    float acc[4][4] = {};
    for (int it = 0; it < 36; it++){
        int n  = it >> 2;
        int c0 = (it & 3) << 5;
        int dy = n/3 - 1, dx = n%3 - 1;
        if (tid < 128){
            int o = tid >> 2, seg = tid & 3;
            cpa16(bsu + (o*HPAD + seg*4)*4, g_w2h + (size_t)n*32*CM + o*CM + c0 + seg*8);
        }
        CPA_COMMIT();
        // A: im2col from fp16 NHWC g_yh, 16B = 8 channels per thread
        #pragma unroll
        for (int p = 0; p < 2; p++){
            int px = warp*16 + p*8 + sub;
            int pg = p0 + px, h = pg / Ww, w = pg % Ww;
            int sy = h + dy, sx = w + dx;
            bool ok = (sy >= 0) & (sy < Hh) & (sx >= 0) & (sx < Ww);
            uint4 t = make_uint4(0u,0u,0u,0u);
            if (ok)
                t = *(const uint4*)(g_yh + (size_t)(b_*HW + sy*Ww + sx)*CM + c0 + grp*8);
            *(uint4*)(As + px*HPAD + grp*4) = t;
        }
        CPA_WAIT0();
        __syncthreads();
        const uint32_t* Ab = As + (warp*16 + gid)*HPAD;
        const uint32_t* Bb = Bs + gid*HPAD;
        #pragma unroll
        for (int kk = 0; kk < 2; kk++){
            int kb = kk*8 + tig;
            uint32_t a0 = Ab[kb], a1 = Ab[8*HPAD + kb];
            uint32_t a2 = Ab[kb + 4], a3 = Ab[8*HPAD + kb + 4];
            #pragma unroll
            for (int nt = 0; nt < 4; nt++){
                uint32_t b0 = Bb[(nt*8)*HPAD + kb];
                uint32_t b1 = Bb[(nt*8)*HPAD + kb + 4];
                MMA_F16(acc[nt], a0,a1,a2,a3, b0,b1);
            }
        }
        __syncthreads();
    }
    #pragma unroll
    for (int half = 0; half < 2; half++){
        int px = warp*16 + gid + half*8;
        float* pp = g_pred + (size_t)(b_*HW + p0 + px)*NOFF;
        #pragma unroll
        for (int nt = 0; nt < 4; nt++){
            int c = nt*8 + 2*tig;
            float v0 = acc[nt][half*2 + 0] + sB[c];
            float v1 = acc[nt][half*2 + 1] + sB[c+1];
            if (c >= 18)   v0 = 1.f/(1.f + __expf(-v0));
            if (c+1 >= 18) v1 = 1.f/(1.f + __expf(-v1));
            if (c < NOFF)   pp[c]   = v0;
            if (c+1 < NOFF) pp[c+1] = v1;
        }
    }
}

// ---------------- K3: deform conv via fp16 mma, double-buffered, 8ch gather ----------------
#define K3_F_AS0  0
#define K3_F_AS1  (128*HPAD)
#define K3_F_BS0  (2*128*HPAD)
#define K3_F_BS1  (3*128*HPAD)
#define K3_F_IDX  (4*128*HPAD)
#define K3_F_WT   (K3_F_IDX + 4608)
#define K3_F_S    (K3_F_WT + 4608)
#define K3_F_T    (K3_F_S + 128)
#define K3_SMEM_F (K3_F_T + 128)

__global__ void __launch_bounds__(256, 2) k3_deform_mma(const float* __restrict__ dcnb,
        const float* __restrict__ g2, const float* __restrict__ b2,
        const float* __restrict__ m2, const float* __restrict__ v2){
    extern __shared__ float sm[];
    uint32_t* AsB[2] = { (uint32_t*)(sm + K3_F_AS0), (uint32_t*)(sm + K3_F_AS1) };
    uint32_t* BsB[2] = { (uint32_t*)(sm + K3_F_BS0), (uint32_t*)(sm + K3_F_BS1) };
    int4*   sIdx = (int4*)(sm + K3_F_IDX);
    float4* sWt  = (float4*)(sm + K3_F_WT);
    float* sS = sm + K3_F_S;
    float* sT = sm + K3_F_T;

    int blk = blockIdx.x;
    int b_ = blk / 50;
    int p0 = (blk % 50) * 128;
    int tid = threadIdx.x, warp = tid >> 5, lane = tid & 31;

    // setup: precompute bilinear corner indices + mask/validity-folded weights
    for (int pr = tid; pr < 128*9; pr += 256){
        int p = pr / 9, nn = pr % 9;
        int pg = p0 + p, h = pg / Ww, w = pg % Ww;
        size_t pb = (size_t)(b_*HW + pg) * NOFF;
        float py = (float)(h - 1 + nn/3) + g_pred[pb + 2*nn];
        float qx = (float)(w - 1 + nn%3) + g_pred[pb + 2*nn + 1];
        float mk = g_pred[pb + 18 + nn];
        float y0f = floorf(py), x0f = floorf(qx);
        float wy = py - y0f, wx = qx - x0f;
        int iy0 = (int)y0f, ix0 = (int)x0f, iy1 = iy0 + 1, ix1 = ix0 + 1;
        float vy0 = (iy0 >= 0 && iy0 < Hh) ? 1.f : 0.f;
        float vy1 = (iy1 >= 0 && iy1 < Hh) ? 1.f : 0.f;
        float vx0 = (ix0 >= 0 && ix0 < Ww) ? 1.f : 0.f;
        float vx1 = (ix1 >= 0 && ix1 < Ww) ? 1.f : 0.f;
        int cy0 = min(max(iy0,0),Hh-1), cy1 = min(max(iy1,0),Hh-1);
        int cx0 = min(max(ix0,0),Ww-1), cx1 = min(max(ix1,0),Ww-1);
        int base = b_*HW;
        int4 id;
        id.x = (base + cy0*Ww + cx0)*CM;
        id.y = (base + cy0*Ww + cx1)*CM;
        id.z = (base + cy1*Ww + cx0)*CM;
        id.w = (base + cy1*Ww + cx1)*CM;
        float4 wt;
        wt.x = (1.f-wy)*(1.f-wx)*mk*vy0*vx0;
        wt.y = (1.f-wy)*wx      *mk*vy0*vx1;
        wt.z = wy*(1.f-wx)      *mk*vy1*vx0;
        wt.w = wy*wx            *mk*vy1*vx1;
        sIdx[pr] = id;
        sWt[pr]  = wt;
    }
    if (tid < 128){
        float s = g2[tid] * rsqrtf(v2[tid] + EPSF);
        sS[tid] = s;
        sT[tid] = dcnb[tid]*s + b2[tid] - m2[tid]*s;
    }
    __syncthreads();

    int wm = warp & 3, wnn = warp >> 2, gid = lane >> 2, tig = lane & 3;
    int sub = lane >> 2, grp = lane & 3;   // 8 px x 4 channel-groups (8ch each)
    float acc[2][8][4] = {};

    auto fillB = [&](int it, int buf){
        int n = it >> 2, c0 = (it & 3) << 5;
        const __half* wn = g_wdh + (size_t)n*(CM*CM) + c0;
        uint32_t bu = s2u(BsB[buf]);
        #pragma unroll
        for (int i = 0; i < 2; i++){
            int u = i*256 + tid; int o = u >> 2, seg = u & 3;
            cpa16(bu + (o*HPAD + seg*4)*4, wn + o*CM + seg*8);
        }
    };
    // gather: 8-channel (16B) loads per corner, fp32 bilinear math
    auto fillA = [&](int it, int buf){
        int n = it >> 2, c0 = (it & 3) << 5;
        const __half* yb = g_yh + c0 + grp*8;
        uint32_t* Ad = AsB[buf];
        #pragma unroll
        for (int p = 0; p < 2; p++){
            int px = warp*16 + p*8 + sub;
            int pr = px*9 + n;
            int4   id = sIdx[pr];
            float4 wt = sWt[pr];
            uint4 c00 = *(const uint4*)(yb + id.x);
            uint4 c01 = *(const uint4*)(yb + id.y);
            uint4 c10 = *(const uint4*)(yb + id.z);
            uint4 c11 = *(const uint4*)(yb + id.w);
            uint4 t;
            #pragma unroll
            for (int q = 0; q < 4; q++){
                float2 f0 = __half22float2(((__half2*)&c00)[q]);
                float2 f1 = __half22float2(((__half2*)&c01)[q]);
                float2 f2 = __half22float2(((__half2*)&c10)[q]);
                float2 f3 = __half22float2(((__half2*)&c11)[q]);
                float2 v;
                v.x = wt.x*f0.x + wt.y*f1.x + wt.z*f2.x + wt.w*f3.x;
                v.y = wt.x*f0.y + wt.y*f1.y + wt.z*f2.y + wt.w*f3.y;
                ((__half2*)&t)[q] = __float22half2_rn(v);
            }
            *(uint4*)(Ad + px*HPAD + grp*4) = t;
        }
    };

    // prologue
    fillB(0, 0); CPA_COMMIT();
    fillA(0, 0);
    CPA_WAIT0();
    __syncthreads();

    int cur = 0;
    for (int it = 0; it < 36; it++){
        int nb = cur ^ 1;
        if (it < 35){ fillB(it+1, nb); CPA_COMMIT(); }
        mma_f16_128(AsB[cur], BsB[cur], wm, wnn, gid, tig, acc);
        if (it < 35) fillA(it+1, nb);
        CPA_WAIT0();
        __syncthreads();
        cur = nb;
    }

    // epilogue: bn2 + silu -> g_zh (fp16 NHWC)
    #pragma unroll
    for (int mt = 0; mt < 2; mt++){
        int r0 = wm*32 + mt*16 + gid;
        __half2* z0 = (__half2*)(g_zh + (size_t)(b_*HW + p0 + r0)*CM);
        __half2* z1 = (__half2*)(g_zh + (size_t)(b_*HW + p0 + r0 + 8)*CM);
        #pragma unroll
        for (int nt = 0; nt < 8; nt++){
            int cb = wnn*64 + nt*8 + 2*tig;
            float s0 = sS[cb], s1 = sS[cb+1], t0 = sT[cb], t1 = sT[cb+1];
            z0[cb>>1] = __float22half2_rn(make_float2(
                silu_f(acc[mt][nt][0]*s0 + t0), silu_f(acc[mt][nt][1]*s1 + t1)));
            z1[cb>>1] = __float22half2_rn(make_float2(
                silu_f(acc[mt][nt][2]*s0 + t0), silu_f(acc[mt][nt][3]*s1 + t1)));
        }
    }
}

// ---------------- K4: conv1x1(128->256) + bn3 + silu + residual -> out (NCHW) ----------------
__global__ void __launch_bounds__(256, 2) k4_mma(const float* __restrict__ x, float* __restrict__ out,
        const float* __restrict__ g3, const float* __restrict__ b3,
        const float* __restrict__ m3, const float* __restrict__ v3){
    __shared__ __align__(16) uint32_t As[128*HPAD];
    __shared__ __align__(16) uint32_t Bs[128*HPAD];
    __shared__ float sS[128], sT[128];
    int blk = blockIdx.x;
    int b_ = blk / 50;
    int p0 = (blk % 50) * 128;
    int o0g = blockIdx.y * 128;
    int tid = threadIdx.x, warp = tid >> 5, lane = tid & 31;
    int wm = warp & 3, wnn = warp >> 2, gid = lane >> 2, tig = lane & 3;
    if (tid < 128){
        int o = o0g + tid;
        float s = g3[o] * rsqrtf(v3[o] + EPSF);
        sS[tid] = s;
        sT[tid] = b3[o] - m3[o]*s;
    }
    float acc[2][8][4] = {};
    const __half* zt = g_zh + (size_t)(b_*HW + p0)*CM;
    const __half* wb = g_w3h + (size_t)o0g*CM;
    uint32_t asu = s2u(As), bsu = s2u(Bs);
    for (int kc = 0; kc < 4; kc++){
        int k0 = kc*32;
        #pragma unroll
        for (int i = 0; i < 2; i++){
            int u = i*256 + tid; int r = u >> 2, seg = u & 3;
            cpa16(asu + (r*HPAD + seg*4)*4, zt + (size_t)r*CM + k0 + seg*8);
            cpa16(bsu + (r*HPAD + seg*4)*4, wb + r*CM + k0 + seg*8);
        }
        CPA_COMMIT();
        CPA_WAIT0();
        __syncthreads();
        mma_f16_128(As, Bs, wm, wnn, gid, tig, acc);
        __syncthreads();
    }
    #pragma unroll
    for (int mt = 0; mt < 2; mt++){
        int pg0 = p0 + wm*32 + mt*16 + gid;
        #pragma unroll
        for (int nt = 0; nt < 8; nt++){
            int o = o0g + wnn*64 + nt*8 + 2*tig;
            float s0 = sS[o - o0g], s1 = sS[o - o0g + 1];
            float t0 = sT[o - o0g], t1 = sT[o - o0g + 1];
            size_t i00 = ((size_t)b_*C2 + o)*HW + pg0;
            size_t i01 = i00 + HW;
            out[i00]     = x[i00]     + silu_f(acc[mt][nt][0]*s0 + t0);
            out[i01]     = x[i01]     + silu_f(acc[mt][nt][1]*s1 + t1);
            out[i00 + 8] = x[i00 + 8] + silu_f(acc[mt][nt][2]*s0 + t0);
            out[i01 + 8] = x[i01 + 8] + silu_f(acc[mt][nt][3]*s1 + t1);
        }
    }
}

// ---------------- launch ----------------
extern "C" void kernel_launch(void* const* d_in, const int* in_sizes, int n_in,
                              void* d_out, int out_size){
    const float* x     = (const float*)d_in[0];
    const float* cv1_w = (const float*)d_in[1];
    const float* bn1g  = (const float*)d_in[2];
    const float* bn1b  = (const float*)d_in[3];
    const float* bn1m  = (const float*)d_in[4];
    const float* bn1v  = (const float*)d_in[5];
    const float* off_w = (const float*)d_in[6];
    const float* off_b = (const float*)d_in[7];
    const float* dcn_w = (const float*)d_in[8];
    const float* dcn_b = (const float*)d_in[9];
    const float* bn2g  = (const float*)d_in[10];
    const float* bn2b  = (const float*)d_in[11];
    const float* bn2m  = (const float*)d_in[12];
    const float* bn2v  = (const float*)d_in[13];
    const float* cv3_w = (const float*)d_in[14];
    const float* bn3g  = (const float*)d_in[15];
    const float* bn3b  = (const float*)d_in[16];
    const float* bn3m  = (const float*)d_in[17];
    const float* bn3v  = (const float*)d_in[18];
    float* out = (float*)d_out;

    prep_w<<<(N9*CM*CM + 255)/256, 256>>>(cv1_w, off_w, dcn_w, cv3_w);
    k1_mma<<<BSZ*50, 256>>>(x, bn1g, bn1b, bn1m, bn1v);
    k2_mma<<<BSZ*50, 256>>>(off_b);

    int smem_bytes = K3_SMEM_F * 4;  // 78848 B
    cudaFuncSetAttribute(k3_deform_mma, cudaFuncAttributeMaxDynamicSharedMemorySize, smem_bytes);
    k3_deform_mma<<<BSZ*50, 256, smem_bytes>>>(dcn_b, bn2g, bn2b, bn2m, bn2v);

    k4_mma<<<dim3(BSZ*50, 2), 256>>>(x, out, bn3g, bn3b, bn3m, bn3v);
}

// round 10
// speedup vs baseline: 4.7754x; 1.0164x over previous
#include <cuda_runtime.h>
#include <cuda_fp16.h>
#include <math.h>
#include <stdint.h>

#define BSZ   8
#define C1    256
#define C2    256
#define CM    128
#define Hh    80
#define Ww    80
#define HW    6400
#define N9    9
#define KCN   1152      // CM * 9
#define NOFF  27
#define EPSF  1e-5f

// ---------------- scratch (device globals; no runtime alloc) ----------------
__device__ __align__(16) __half g_xh  [BSZ*HW*C1];    // NHWC x (fp16)
__device__ __align__(16) __half g_yh  [BSZ*HW*CM];    // NHWC y (fp16)
__device__ __align__(16) __half g_zh  [BSZ*HW*CM];    // NHWC z (fp16)
__device__ __align__(16) float  g_pred[BSZ*HW*NOFF];  // per-pixel [27] fp32
__device__ __align__(16) __half g_w1h [CM*C1];        // [o][k]
__device__ __align__(16) __half g_w2h [N9*32*CM];     // [n][o pad 32][c]
__device__ __align__(16) __half g_wdh [N9*CM*CM];     // [n][o][c]
__device__ __align__(16) __half g_w3h [C2*CM];        // [o][k]

__device__ __forceinline__ float silu_f(float v){ return v / (1.f + __expf(-v)); }
__device__ __forceinline__ uint32_t s2u(const void* p){
    return (uint32_t)__cvta_generic_to_shared(p);
}
__device__ __forceinline__ void cpa16(uint32_t s, const void* g){
    asm volatile("cp.async.cg.shared.global [%0], [%1], 16;" :: "r"(s), "l"(g));
}
#define CPA_COMMIT() asm volatile("cp.async.commit_group;" ::: "memory")
#define CPA_WAIT0()  asm volatile("cp.async.wait_group 0;" ::: "memory")

// row pitch in u32 (16 u32 = 32 halves data + pad 4) -> 80B rows, uint4-aligned
#define HPAD 20

#define MMA_F16(accq, a0,a1,a2,a3, b0,b1) \
    asm volatile("mma.sync.aligned.m16n8k16.row.col.f32.f16.f16.f32 " \
        "{%0,%1,%2,%3}, {%4,%5,%6,%7}, {%8,%9}, {%0,%1,%2,%3};" \
        : "+f"((accq)[0]), "+f"((accq)[1]), "+f"((accq)[2]), "+f"((accq)[3]) \
        : "r"(a0), "r"(a1), "r"(a2), "r"(a3), "r"(b0), "r"(b1))

__device__ __forceinline__ void ldsm4(uint32_t* r, uint32_t a){
    asm volatile("ldmatrix.sync.aligned.m8n8.x4.shared.b16 {%0,%1,%2,%3}, [%4];"
        : "=r"(r[0]), "=r"(r[1]), "=r"(r[2]), "=r"(r[3]) : "r"(a));
}

// 128x128 warp-tiled fp16 mma (k-chunk 32) with ldmatrix fragment loads.
// As/Bs given as u32 shared addresses of [128][HPAD] u32 tiles.
__device__ __forceinline__ void mma_f16_128_ldsm(uint32_t asu, uint32_t bsu,
        int wm, int wnn, int lane, float acc[2][8][4]){
    int l7 = lane & 7;
    uint32_t aAddr = asu + (uint32_t)((wm*32 + ((lane>>3)&1)*8 + l7)*HPAD)*4 + (lane>>4)*16;
    uint32_t bAddr = bsu + (uint32_t)((wnn*64 + ((lane>>4)&1)*8 + l7)*HPAD)*4 + ((lane>>3)&1)*16;
    uint32_t a[2][2][4];
    #pragma unroll
    for (int mt = 0; mt < 2; mt++)
        #pragma unroll
        for (int kk = 0; kk < 2; kk++)
            ldsm4(a[mt][kk], aAddr + (uint32_t)(mt*16*HPAD + kk*8)*4);
    #pragma unroll
    for (int ntp = 0; ntp < 4; ntp++){
        #pragma unroll
        for (int kk = 0; kk < 2; kk++){
            uint32_t b[4];
            ldsm4(b, bAddr + (uint32_t)(ntp*16*HPAD + kk*8)*4);
            #pragma unroll
            for (int mt = 0; mt < 2; mt++){
                MMA_F16(acc[mt][2*ntp],   a[mt][kk][0],a[mt][kk][1],a[mt][kk][2],a[mt][kk][3], b[0],b[1]);
                MMA_F16(acc[mt][2*ntp+1], a[mt][kk][0],a[mt][kk][1],a[mt][kk][2],a[mt][kk][3], b[2],b[3]);
            }
        }
    }
}

// ---------------- K0a: weight conversions/reshapes to fp16 ----------------
__global__ void prep_w(const float* __restrict__ w1, const float* __restrict__ w2,
                       const float* __restrict__ wd, const float* __restrict__ w3){
    int i = blockIdx.x*blockDim.x + threadIdx.x;
    if (i < CM*C1)  g_w1h[i] = __float2half(w1[i]);
    if (i < C2*CM)  g_w3h[i] = __float2half(w3[i]);
    if (i < N9*32*CM){
        int n = i/(32*CM); int o = (i/CM) & 31; int c = i % CM;
        g_w2h[i] = (o < NOFF) ? __float2half(w2[o*KCN + c*9 + n]) : __float2half(0.f);
    }
    if (i < N9*CM*CM){
        int n = i/(CM*CM); int rest = i%(CM*CM); int o = rest/CM, c = rest%CM;
        g_wdh[i] = __float2half(wd[o*KCN + c*9 + n]);
    }
}

// ---------------- K0b: x NCHW fp32 -> NHWC fp16 ----------------
__global__ void __launch_bounds__(256) prep_xh(const float* __restrict__ x){
    __shared__ float t[32][33];
    int b  = blockIdx.z;
    int c0 = blockIdx.y * 32;
    int p0 = blockIdx.x * 32;
    int tx = threadIdx.x & 31, ty = threadIdx.x >> 5;   // 32 x 8
    #pragma unroll
    for (int i = 0; i < 4; i++)
        t[ty + 8*i][tx] = x[((size_t)b*C1 + c0 + ty + 8*i)*HW + p0 + tx];
    __syncthreads();
    #pragma unroll
    for (int i = 0; i < 4; i++)
        g_xh[((size_t)b*HW + p0 + ty + 8*i)*C1 + c0 + tx] = __float2half(t[tx][ty + 8*i]);
}

// ---------------- K1: conv1x1(256->128) + bn1 + silu -> g_yh (NHWC fp16) ----------------
__global__ void __launch_bounds__(256, 2) k1_mma(
        const float* __restrict__ g1, const float* __restrict__ b1,
        const float* __restrict__ m1, const float* __restrict__ v1){
    __shared__ __align__(16) uint32_t As[128*HPAD];
    __shared__ __align__(16) uint32_t Bs[128*HPAD];
    __shared__ float sS[128], sT[128];
    int blk = blockIdx.x;
    int b_ = blk / 50;
    int p0 = (blk % 50) * 128;
    int tid = threadIdx.x, warp = tid >> 5, lane = tid & 31;
    int wm = warp & 3, wnn = warp >> 2, gid = lane >> 2, tig = lane & 3;
    if (tid < 128){
        float s = g1[tid] * rsqrtf(v1[tid] + EPSF);
        sS[tid] = s;
        sT[tid] = b1[tid] - m1[tid]*s;
    }
    float acc[2][8][4] = {};
    const __half* xt = g_xh + (size_t)(b_*HW + p0)*C1;
    uint32_t asu = s2u(As), bsu = s2u(Bs);
    for (int kc = 0; kc < 8; kc++){
        int k0 = kc*32;
        #pragma unroll
        for (int i = 0; i < 2; i++){
            int u = i*256 + tid; int r = u >> 2, seg = u & 3;
            cpa16(asu + (r*HPAD + seg*4)*4, xt + (size_t)r*C1 + k0 + seg*8);
            cpa16(bsu + (r*HPAD + seg*4)*4, g_w1h + r*C1 + k0 + seg*8);
        }
        CPA_COMMIT();
        CPA_WAIT0();
        __syncthreads();
        mma_f16_128_ldsm(asu, bsu, wm, wnn, lane, acc);
        __syncthreads();
    }
    #pragma unroll
    for (int mt = 0; mt < 2; mt++){
        int r0 = wm*32 + mt*16 + gid;
        __half2* z0 = (__half2*)(g_yh + (size_t)(b_*HW + p0 + r0)*CM);
        __half2* z1 = (__half2*)(g_yh + (size_t)(b_*HW + p0 + r0 + 8)*CM);
        #pragma unroll
        for (int nt = 0; nt < 8; nt++){
            int cb = wnn*64 + nt*8 + 2*tig;
            float s0 = sS[cb], s1 = sS[cb+1], t0 = sT[cb], t1 = sT[cb+1];
            z0[cb>>1] = __float22half2_rn(make_float2(
                silu_f(acc[mt][nt][0]*s0 + t0), silu_f(acc[mt][nt][1]*s1 + t1)));
            z1[cb>>1] = __float22half2_rn(make_float2(
                silu_f(acc[mt][nt][2]*s0 + t0), silu_f(acc[mt][nt][3]*s1 + t1)));
        }
    }
}

// ---------------- K2: conv3x3(128->27) via fp16 mma (implicit im2col) -> g_pred ----------------
__global__ void __launch_bounds__(256, 4) k2_mma(const float* __restrict__ offb){
    __shared__ __align__(16) uint32_t As[128*HPAD];
    __shared__ __align__(16) uint32_t Bs[32*HPAD];
    __shared__ float sB[32];
    int blk = blockIdx.x;
    int b_ = blk / 50;
    int p0 = (blk % 50) * 128;
    int tid = threadIdx.x, warp = tid >> 5, lane = tid & 31;
    int gid = lane >> 2, tig = lane & 3;
    int sub = lane >> 2, grp = lane & 3;     // 8 px x 4 channel-groups (8ch each)
    int l7 = lane & 7;
    if (tid < 32) sB[tid] = (tid < NOFF) ? offb[tid] : 0.f;
    uint32_t asu = s2u(As), bsu = s2u(Bs);
    uint32_t aAddr = asu + (uint32_t)((warp*16 + ((lane>>3)&1)*8 + l7)*HPAD)*4 + (lane>>4)*16;
    uint32_t bAddr = bsu + (uint32_t)((((lane>>4)&1)*8 + l7)*HPAD)*4 + ((lane>>3)&1)*16;

    float acc[4][4] = {};
    for (int it = 0; it < 36; it++){
        int n  = it >> 2;
        int c0 = (it & 3) << 5;
        int dy = n/3 - 1, dx = n%3 - 1;
        if (tid < 128){
            int o = tid >> 2, seg = tid & 3;
            cpa16(bsu + (o*HPAD + seg*4)*4, g_w2h + (size_t)n*32*CM + o*CM + c0 + seg*8);
        }
        CPA_COMMIT();
        #pragma unroll
        for (int p = 0; p < 2; p++){
            int px = warp*16 + p*8 + sub;
            int pg = p0 + px, h = pg / Ww, w = pg % Ww;
            int sy = h + dy, sx = w + dx;
            bool ok = (sy >= 0) & (sy < Hh) & (sx >= 0) & (sx < Ww);
            uint4 t = make_uint4(0u,0u,0u,0u);
            if (ok)
                t = *(const uint4*)(g_yh + (size_t)(b_*HW + sy*Ww + sx)*CM + c0 + grp*8);
            *(uint4*)(As + px*HPAD + grp*4) = t;
        }
        CPA_WAIT0();
        __syncthreads();
        uint32_t a[2][4];
        #pragma unroll
        for (int kk = 0; kk < 2; kk++)
            ldsm4(a[kk], aAddr + (uint32_t)(kk*8)*4);
        #pragma unroll
        for (int ntp = 0; ntp < 2; ntp++){
            #pragma unroll
            for (int kk = 0; kk < 2; kk++){
                uint32_t b[4];
                ldsm4(b, bAddr + (uint32_t)(ntp*16*HPAD + kk*8)*4);
                MMA_F16(acc[2*ntp],   a[kk][0],a[kk][1],a[kk][2],a[kk][3], b[0],b[1]);
                MMA_F16(acc[2*ntp+1], a[kk][0],a[kk][1],a[kk][2],a[kk][3], b[2],b[3]);
            }
        }
        __syncthreads();
    }
    #pragma unroll
    for (int half = 0; half < 2; half++){
        int px = warp*16 + gid + half*8;
        float* pp = g_pred + (size_t)(b_*HW + p0 + px)*NOFF;
        #pragma unroll
        for (int nt = 0; nt < 4; nt++){
            int c = nt*8 + 2*tig;
            float v0 = acc[nt][half*2 + 0] + sB[c];
            float v1 = acc[nt][half*2 + 1] + sB[c+1];
            if (c >= 18)   v0 = 1.f/(1.f + __expf(-v0));
            if (c+1 >= 18) v1 = 1.f/(1.f + __expf(-v1));
            if (c < NOFF)   pp[c]   = v0;
            if (c+1 < NOFF) pp[c+1] = v1;
        }
    }
}

// ---------------- K3: deform conv via fp16 mma, double-buffered, ldmatrix ----------------
#define K3_F_AS0  0
#define K3_F_AS1  (128*HPAD)
#define K3_F_BS0  (2*128*HPAD)
#define K3_F_BS1  (3*128*HPAD)
#define K3_F_IDX  (4*128*HPAD)
#define K3_F_WT   (K3_F_IDX + 4608)
#define K3_F_S    (K3_F_WT + 4608)
#define K3_F_T    (K3_F_S + 128)
#define K3_SMEM_F (K3_F_T + 128)

__global__ void __launch_bounds__(256, 2) k3_deform_mma(const float* __restrict__ dcnb,
        const float* __restrict__ g2, const float* __restrict__ b2,
        const float* __restrict__ m2, const float* __restrict__ v2){
    extern __shared__ float sm[];
    uint32_t* AsB[2] = { (uint32_t*)(sm + K3_F_AS0), (uint32_t*)(sm + K3_F_AS1) };
    uint32_t* BsB[2] = { (uint32_t*)(sm + K3_F_BS0), (uint32_t*)(sm + K3_F_BS1) };
    int4*   sIdx = (int4*)(sm + K3_F_IDX);
    float4* sWt  = (float4*)(sm + K3_F_WT);
    float* sS = sm + K3_F_S;
    float* sT = sm + K3_F_T;

    int blk = blockIdx.x;
    int b_ = blk / 50;
    int p0 = (blk % 50) * 128;
    int tid = threadIdx.x, warp = tid >> 5, lane = tid & 31;

    // setup: precompute bilinear corner indices + mask/validity-folded weights
    for (int pr = tid; pr < 128*9; pr += 256){
        int p = pr / 9, nn = pr % 9;
        int pg = p0 + p, h = pg / Ww, w = pg % Ww;
        size_t pb = (size_t)(b_*HW + pg) * NOFF;
        float py = (float)(h - 1 + nn/3) + g_pred[pb + 2*nn];
        float qx = (float)(w - 1 + nn%3) + g_pred[pb + 2*nn + 1];
        float mk = g_pred[pb + 18 + nn];
        float y0f = floorf(py), x0f = floorf(qx);
        float wy = py - y0f, wx = qx - x0f;
        int iy0 = (int)y0f, ix0 = (int)x0f, iy1 = iy0 + 1, ix1 = ix0 + 1;
        float vy0 = (iy0 >= 0 && iy0 < Hh) ? 1.f : 0.f;
        float vy1 = (iy1 >= 0 && iy1 < Hh) ? 1.f : 0.f;
        float vx0 = (ix0 >= 0 && ix0 < Ww) ? 1.f : 0.f;
        float vx1 = (ix1 >= 0 && ix1 < Ww) ? 1.f : 0.f;
        int cy0 = min(max(iy0,0),Hh-1), cy1 = min(max(iy1,0),Hh-1);
        int cx0 = min(max(ix0,0),Ww-1), cx1 = min(max(ix1,0),Ww-1);
        int base = b_*HW;
        int4 id;
        id.x = (base + cy0*Ww + cx0)*CM;
        id.y = (base + cy0*Ww + cx1)*CM;
        id.z = (base + cy1*Ww + cx0)*CM;
        id.w = (base + cy1*Ww + cx1)*CM;
        float4 wt;
        wt.x = (1.f-wy)*(1.f-wx)*mk*vy0*vx0;
        wt.y = (1.f-wy)*wx      *mk*vy0*vx1;
        wt.z = wy*(1.f-wx)      *mk*vy1*vx0;
        wt.w = wy*wx            *mk*vy1*vx1;
        sIdx[pr] = id;
        sWt[pr]  = wt;
    }
    if (tid < 128){
        float s = g2[tid] * rsqrtf(v2[tid] + EPSF);
        sS[tid] = s;
        sT[tid] = dcnb[tid]*s + b2[tid] - m2[tid]*s;
    }
    __syncthreads();

    int wm = warp & 3, wnn = warp >> 2, gid = lane >> 2, tig = lane & 3;
    int sub = lane >> 2, grp = lane & 3;   // 8 px x 4 channel-groups (8ch each)
    float acc[2][8][4] = {};
    uint32_t asuB[2] = { s2u(AsB[0]), s2u(AsB[1]) };
    uint32_t bsuB[2] = { s2u(BsB[0]), s2u(BsB[1]) };

    auto fillB = [&](int it, int buf){
        int n = it >> 2, c0 = (it & 3) << 5;
        const __half* wn = g_wdh + (size_t)n*(CM*CM) + c0;
        uint32_t bu = bsuB[buf];
        #pragma unroll
        for (int i = 0; i < 2; i++){
            int u = i*256 + tid; int o = u >> 2, seg = u & 3;
            cpa16(bu + (o*HPAD + seg*4)*4, wn + o*CM + seg*8);
        }
    };
    auto fillA = [&](int it, int buf){
        int n = it >> 2, c0 = (it & 3) << 5;
        const __half* yb = g_yh + c0 + grp*8;
        uint32_t* Ad = AsB[buf];
        #pragma unroll
        for (int p = 0; p < 2; p++){
            int px = warp*16 + p*8 + sub;
            int pr = px*9 + n;
            int4   id = sIdx[pr];
            float4 wt = sWt[pr];
            uint4 c00 = *(const uint4*)(yb + id.x);
            uint4 c01 = *(const uint4*)(yb + id.y);
            uint4 c10 = *(const uint4*)(yb + id.z);
            uint4 c11 = *(const uint4*)(yb + id.w);
            uint4 t;
            #pragma unroll
            for (int q = 0; q < 4; q++){
                float2 f0 = __half22float2(((__half2*)&c00)[q]);
                float2 f1 = __half22float2(((__half2*)&c01)[q]);
                float2 f2 = __half22float2(((__half2*)&c10)[q]);
                float2 f3 = __half22float2(((__half2*)&c11)[q]);
                float2 v;
                v.x = wt.x*f0.x + wt.y*f1.x + wt.z*f2.x + wt.w*f3.x;
                v.y = wt.x*f0.y + wt.y*f1.y + wt.z*f2.y + wt.w*f3.y;
                ((__half2*)&t)[q] = __float22half2_rn(v);
            }
            *(uint4*)(Ad + px*HPAD + grp*4) = t;
        }
    };

    // prologue
    fillB(0, 0); CPA_COMMIT();
    fillA(0, 0);
    CPA_WAIT0();
    __syncthreads();

    int cur = 0;
    for (int it = 0; it < 36; it++){
        int nb = cur ^ 1;
        if (it < 35){ fillB(it+1, nb); CPA_COMMIT(); }
        mma_f16_128_ldsm(asuB[cur], bsuB[cur], wm, wnn, lane, acc);
        if (it < 35) fillA(it+1, nb);
        CPA_WAIT0();
        __syncthreads();
        cur = nb;
    }

    // epilogue: bn2 + silu -> g_zh (fp16 NHWC)
    #pragma unroll
    for (int mt = 0; mt < 2; mt++){
        int r0 = wm*32 + mt*16 + gid;
        __half2* z0 = (__half2*)(g_zh + (size_t)(b_*HW + p0 + r0)*CM);
        __half2* z1 = (__half2*)(g_zh + (size_t)(b_*HW + p0 + r0 + 8)*CM);
        #pragma unroll
        for (int nt = 0; nt < 8; nt++){
            int cb = wnn*64 + nt*8 + 2*tig;
            float s0 = sS[cb], s1 = sS[cb+1], t0 = sT[cb], t1 = sT[cb+1];
            z0[cb>>1] = __float22half2_rn(make_float2(
                silu_f(acc[mt][nt][0]*s0 + t0), silu_f(acc[mt][nt][1]*s1 + t1)));
            z1[cb>>1] = __float22half2_rn(make_float2(
                silu_f(acc[mt][nt][2]*s0 + t0), silu_f(acc[mt][nt][3]*s1 + t1)));
        }
    }
}

// ---------------- K4: conv1x1(128->256) + bn3 + silu + residual -> out (NCHW) ----------------
__global__ void __launch_bounds__(256, 2) k4_mma(const float* __restrict__ x, float* __restrict__ out,
        const float* __restrict__ g3, const float* __restrict__ b3,
        const float* __restrict__ m3, const float* __restrict__ v3){
    __shared__ __align__(16) uint32_t As[128*HPAD];
    __shared__ __align__(16) uint32_t Bs[128*HPAD];
    __shared__ float sS[128], sT[128];
    int blk = blockIdx.x;
    int b_ = blk / 50;
    int p0 = (blk % 50) * 128;
    int o0g = blockIdx.y * 128;
    int tid = threadIdx.x, warp = tid >> 5, lane = tid & 31;
    int wm = warp & 3, wnn = warp >> 2, gid = lane >> 2, tig = lane & 3;
    if (tid < 128){
        int o = o0g + tid;
        float s = g3[o] * rsqrtf(v3[o] + EPSF);
        sS[tid] = s;
        sT[tid] = b3[o] - m3[o]*s;
    }
    float acc[2][8][4] = {};
    const __half* zt = g_zh + (size_t)(b_*HW + p0)*CM;
    const __half* wb = g_w3h + (size_t)o0g*CM;
    uint32_t asu = s2u(As), bsu = s2u(Bs);
    for (int kc = 0; kc < 4; kc++){
        int k0 = kc*32;
        #pragma unroll
        for (int i = 0; i < 2; i++){
            int u = i*256 + tid; int r = u >> 2, seg = u & 3;
            cpa16(asu + (r*HPAD + seg*4)*4, zt + (size_t)r*CM + k0 + seg*8);
            cpa16(bsu + (r*HPAD + seg*4)*4, wb + r*CM + k0 + seg*8);
        }
        CPA_COMMIT();
        CPA_WAIT0();
        __syncthreads();
        mma_f16_128_ldsm(asu, bsu, wm, wnn, lane, acc);
        __syncthreads();
    }
    #pragma unroll
    for (int mt = 0; mt < 2; mt++){
        int pg0 = p0 + wm*32 + mt*16 + gid;
        #pragma unroll
        for (int nt = 0; nt < 8; nt++){
            int o = o0g + wnn*64 + nt*8 + 2*tig;
            float s0 = sS[o - o0g], s1 = sS[o - o0g + 1];
            float t0 = sT[o - o0g], t1 = sT[o - o0g + 1];
            size_t i00 = ((size_t)b_*C2 + o)*HW + pg0;
            size_t i01 = i00 + HW;
            out[i00]     = x[i00]     + silu_f(acc[mt][nt][0]*s0 + t0);
            out[i01]     = x[i01]     + silu_f(acc[mt][nt][1]*s1 + t1);
            out[i00 + 8] = x[i00 + 8] + silu_f(acc[mt][nt][2]*s0 + t0);
            out[i01 + 8] = x[i01 + 8] + silu_f(acc[mt][nt][3]*s1 + t1);
        }
    }
}

// ---------------- launch ----------------
extern "C" void kernel_launch(void* const* d_in, const int* in_sizes, int n_in,
                              void* d_out, int out_size){
    const float* x     = (const float*)d_in[0];
    const float* cv1_w = (const float*)d_in[1];
    const float* bn1g  = (const float*)d_in[2];
    const float* bn1b  = (const float*)d_in[3];
    const float* bn1m  = (const float*)d_in[4];
    const float* bn1v  = (const float*)d_in[5];
    const float* off_w = (const float*)d_in[6];
    const float* off_b = (const float*)d_in[7];
    const float* dcn_w = (const float*)d_in[8];
    const float* dcn_b = (const float*)d_in[9];
    const float* bn2g  = (const float*)d_in[10];
    const float* bn2b  = (const float*)d_in[11];
    const float* bn2m  = (const float*)d_in[12];
    const float* bn2v  = (const float*)d_in[13];
    const float* cv3_w = (const float*)d_in[14];
    const float* bn3g  = (const float*)d_in[15];
    const float* bn3b  = (const float*)d_in[16];
    const float* bn3m  = (const float*)d_in[17];
    const float* bn3v  = (const float*)d_in[18];
    float* out = (float*)d_out;

    prep_w<<<(N9*CM*CM + 255)/256, 256>>>(cv1_w, off_w, dcn_w, cv3_w);
    prep_xh<<<dim3(200, 8, 8), 256>>>(x);
    k1_mma<<<BSZ*50, 256>>>(bn1g, bn1b, bn1m, bn1v);
    k2_mma<<<BSZ*50, 256>>>(off_b);

    int smem_bytes = K3_SMEM_F * 4;  // 78848 B
    cudaFuncSetAttribute(k3_deform_mma, cudaFuncAttributeMaxDynamicSharedMemorySize, smem_bytes);
    k3_deform_mma<<<BSZ*50, 256, smem_bytes>>>(dcn_b, bn2g, bn2b, bn2m, bn2v);

    k4_mma<<<dim3(BSZ*50, 2), 256>>>(x, out, bn3g, bn3b, bn3m, bn3v);
}

// round 11
// speedup vs baseline: 5.0777x; 1.0633x over previous
#include <cuda_runtime.h>
#include <cuda_fp16.h>
#include <math.h>
#include <stdint.h>

#define BSZ   8
#define C1    256
#define C2    256
#define CM    128
#define Hh    80
#define Ww    80
#define HW    6400
#define N9    9
#define KCN   1152      // CM * 9
#define NOFF  27
#define EPSF  1e-5f

// ---------------- scratch (device globals; no runtime alloc) ----------------
__device__ __align__(16) __half g_xh  [BSZ*HW*C1];    // NHWC x (fp16)
__device__ __align__(16) __half g_yh  [BSZ*HW*CM];    // NHWC y (fp16)
__device__ __align__(16) __half g_zh  [BSZ*HW*CM];    // NHWC z (fp16)
__device__ __align__(16) float  g_pred[BSZ*HW*NOFF];  // per-pixel [27] fp32
__device__ __align__(16) __half g_w1h [CM*C1];        // [o][k]
__device__ __align__(16) __half g_w2h [N9*32*CM];     // [n][o pad 32][c]
__device__ __align__(16) __half g_wdh [N9*CM*CM];     // [n][o][c]
__device__ __align__(16) __half g_w3h [C2*CM];        // [o][k]

__device__ __forceinline__ float silu_f(float v){ return v / (1.f + __expf(-v)); }
__device__ __forceinline__ uint32_t s2u(const void* p){
    return (uint32_t)__cvta_generic_to_shared(p);
}
__device__ __forceinline__ void cpa16(uint32_t s, const void* g){
    asm volatile("cp.async.cg.shared.global [%0], [%1], 16;" :: "r"(s), "l"(g));
}
#define CPA_COMMIT() asm volatile("cp.async.commit_group;" ::: "memory")
#define CPA_WAIT0()  asm volatile("cp.async.wait_group 0;" ::: "memory")

// row pitch in u32: 64 halves data (32 u32) + pad 4 -> 144B rows
#define HPAD 36

#define MMA_F16(accq, a0,a1,a2,a3, b0,b1) \
    asm volatile("mma.sync.aligned.m16n8k16.row.col.f32.f16.f16.f32 " \
        "{%0,%1,%2,%3}, {%4,%5,%6,%7}, {%8,%9}, {%0,%1,%2,%3};" \
        : "+f"((accq)[0]), "+f"((accq)[1]), "+f"((accq)[2]), "+f"((accq)[3]) \
        : "r"(a0), "r"(a1), "r"(a2), "r"(a3), "r"(b0), "r"(b1))

__device__ __forceinline__ void ldsm4(uint32_t* r, uint32_t a){
    asm volatile("ldmatrix.sync.aligned.m8n8.x4.shared.b16 {%0,%1,%2,%3}, [%4];"
        : "=r"(r[0]), "=r"(r[1]), "=r"(r[2]), "=r"(r[3]) : "r"(a));
}

// 128x128 warp-tiled fp16 mma, K-chunk = 64, ldmatrix fragment loads.
__device__ __forceinline__ void mma_f16_128_k64(uint32_t asu, uint32_t bsu,
        int wm, int wnn, int lane, float acc[2][8][4]){
    int l7 = lane & 7;
    uint32_t aBase = asu + (uint32_t)((wm*32 + ((lane>>3)&1)*8 + l7)*HPAD)*4 + (lane>>4)*16;
    uint32_t bBase = bsu + (uint32_t)((wnn*64 + ((lane>>4)&1)*8 + l7)*HPAD)*4 + ((lane>>3)&1)*16;
    #pragma unroll
    for (int kk = 0; kk < 4; kk++){
        uint32_t a[2][4];
        #pragma unroll
        for (int mt = 0; mt < 2; mt++)
            ldsm4(a[mt], aBase + (uint32_t)(mt*16*HPAD)*4 + kk*32);
        #pragma unroll
        for (int ntp = 0; ntp < 4; ntp++){
            uint32_t b[4];
            ldsm4(b, bBase + (uint32_t)(ntp*16*HPAD)*4 + kk*32);
            #pragma unroll
            for (int mt = 0; mt < 2; mt++){
                MMA_F16(acc[mt][2*ntp],   a[mt][0],a[mt][1],a[mt][2],a[mt][3], b[0],b[1]);
                MMA_F16(acc[mt][2*ntp+1], a[mt][0],a[mt][1],a[mt][2],a[mt][3], b[2],b[3]);
            }
        }
    }
}

// ---------------- K0a: weight conversions/reshapes to fp16 ----------------
__global__ void prep_w(const float* __restrict__ w1, const float* __restrict__ w2,
                       const float* __restrict__ wd, const float* __restrict__ w3){
    int i = blockIdx.x*blockDim.x + threadIdx.x;
    if (i < CM*C1)  g_w1h[i] = __float2half(w1[i]);
    if (i < C2*CM)  g_w3h[i] = __float2half(w3[i]);
    if (i < N9*32*CM){
        int n = i/(32*CM); int o = (i/CM) & 31; int c = i % CM;
        g_w2h[i] = (o < NOFF) ? __float2half(w2[o*KCN + c*9 + n]) : __float2half(0.f);
    }
    if (i < N9*CM*CM){
        int n = i/(CM*CM); int rest = i%(CM*CM); int o = rest/CM, c = rest%CM;
        g_wdh[i] = __float2half(wd[o*KCN + c*9 + n]);
    }
}

// ---------------- K0b: x NCHW fp32 -> NHWC fp16 ----------------
__global__ void __launch_bounds__(256) prep_xh(const float* __restrict__ x){
    __shared__ float t[32][33];
    int b  = blockIdx.z;
    int c0 = blockIdx.y * 32;
    int p0 = blockIdx.x * 32;
    int tx = threadIdx.x & 31, ty = threadIdx.x >> 5;   // 32 x 8
    #pragma unroll
    for (int i = 0; i < 4; i++)
        t[ty + 8*i][tx] = x[((size_t)b*C1 + c0 + ty + 8*i)*HW + p0 + tx];
    __syncthreads();
    #pragma unroll
    for (int i = 0; i < 4; i++)
        g_xh[((size_t)b*HW + p0 + ty + 8*i)*C1 + c0 + tx] = __float2half(t[tx][ty + 8*i]);
}

// ---------------- K1: conv1x1(256->128) + bn1 + silu -> g_yh (NHWC fp16) ----------------
__global__ void __launch_bounds__(256, 2) k1_mma(
        const float* __restrict__ g1, const float* __restrict__ b1,
        const float* __restrict__ m1, const float* __restrict__ v1){
    __shared__ __align__(16) uint32_t As[128*HPAD];
    __shared__ __align__(16) uint32_t Bs[128*HPAD];
    __shared__ float sS[128], sT[128];
    int blk = blockIdx.x;
    int b_ = blk / 50;
    int p0 = (blk % 50) * 128;
    int tid = threadIdx.x, warp = tid >> 5, lane = tid & 31;
    int wm = warp & 3, wnn = warp >> 2, gid = lane >> 2, tig = lane & 3;
    if (tid < 128){
        float s = g1[tid] * rsqrtf(v1[tid] + EPSF);
        sS[tid] = s;
        sT[tid] = b1[tid] - m1[tid]*s;
    }
    float acc[2][8][4] = {};
    const __half* xt = g_xh + (size_t)(b_*HW + p0)*C1;
    uint32_t asu = s2u(As), bsu = s2u(Bs);
    for (int kc = 0; kc < 4; kc++){
        int k0 = kc*64;
        #pragma unroll
        for (int i = 0; i < 4; i++){
            int u = i*256 + tid; int r = u >> 3, seg = u & 7;
            cpa16(asu + (r*HPAD + seg*4)*4, xt + (size_t)r*C1 + k0 + seg*8);
            cpa16(bsu + (r*HPAD + seg*4)*4, g_w1h + r*C1 + k0 + seg*8);
        }
        CPA_COMMIT();
        CPA_WAIT0();
        __syncthreads();
        mma_f16_128_k64(asu, bsu, wm, wnn, lane, acc);
        __syncthreads();
    }
    #pragma unroll
    for (int mt = 0; mt < 2; mt++){
        int r0 = wm*32 + mt*16 + gid;
        __half2* z0 = (__half2*)(g_yh + (size_t)(b_*HW + p0 + r0)*CM);
        __half2* z1 = (__half2*)(g_yh + (size_t)(b_*HW + p0 + r0 + 8)*CM);
        #pragma unroll
        for (int nt = 0; nt < 8; nt++){
            int cb = wnn*64 + nt*8 + 2*tig;
            float s0 = sS[cb], s1 = sS[cb+1], t0 = sT[cb], t1 = sT[cb+1];
            z0[cb>>1] = __float22half2_rn(make_float2(
                silu_f(acc[mt][nt][0]*s0 + t0), silu_f(acc[mt][nt][1]*s1 + t1)));
            z1[cb>>1] = __float22half2_rn(make_float2(
                silu_f(acc[mt][nt][2]*s0 + t0), silu_f(acc[mt][nt][3]*s1 + t1)));
        }
    }
}

// ---------------- K2: conv3x3(128->27) via fp16 mma (implicit im2col) -> g_pred ----------------
__global__ void __launch_bounds__(256, 4) k2_mma(const float* __restrict__ offb){
    __shared__ __align__(16) uint32_t As[128*HPAD];
    __shared__ __align__(16) uint32_t Bs[32*HPAD];
    __shared__ float sB[32];
    int blk = blockIdx.x;
    int b_ = blk / 50;
    int p0 = (blk % 50) * 128;
    int tid = threadIdx.x, warp = tid >> 5, lane = tid & 31;
    int gid = lane >> 2, tig = lane & 3;
    int sub = lane >> 3, grp = lane & 7;     // 4 px x 8 channel-groups (8ch each)
    int l7 = lane & 7;
    if (tid < 32) sB[tid] = (tid < NOFF) ? offb[tid] : 0.f;
    uint32_t asu = s2u(As), bsu = s2u(Bs);
    uint32_t aBase = asu + (uint32_t)((warp*16 + ((lane>>3)&1)*8 + l7)*HPAD)*4 + (lane>>4)*16;
    uint32_t bBase = bsu + (uint32_t)((((lane>>4)&1)*8 + l7)*HPAD)*4 + ((lane>>3)&1)*16;

    float acc[4][4] = {};
    for (int it = 0; it < 18; it++){
        int n  = it >> 1;
        int c0 = (it & 1) << 6;
        int dy = n/3 - 1, dx = n%3 - 1;
        // B: 32 o x 64 ch via cp.async (1 per thread)
        {
            int o = tid >> 3, seg = tid & 7;
            cpa16(bsu + (o*HPAD + seg*4)*4, g_w2h + (size_t)n*32*CM + o*CM + c0 + seg*8);
        }
        CPA_COMMIT();
        // A: im2col 16B loads, 4 passes of (4 px x 8 groups)
        #pragma unroll
        for (int p = 0; p < 4; p++){
            int px = warp*16 + p*4 + sub;
            int pg = p0 + px, h = pg / Ww, w = pg % Ww;
            int sy = h + dy, sx = w + dx;
            bool ok = (sy >= 0) & (sy < Hh) & (sx >= 0) & (sx < Ww);
            uint4 t = make_uint4(0u,0u,0u,0u);
            if (ok)
                t = *(const uint4*)(g_yh + (size_t)(b_*HW + sy*Ww + sx)*CM + c0 + grp*8);
            *(uint4*)(As + px*HPAD + grp*4) = t;
        }
        CPA_WAIT0();
        __syncthreads();
        #pragma unroll
        for (int kk = 0; kk < 4; kk++){
            uint32_t a[4];
            ldsm4(a, aBase + kk*32);
            #pragma unroll
            for (int ntp = 0; ntp < 2; ntp++){
                uint32_t b[4];
                ldsm4(b, bBase + (uint32_t)(ntp*16*HPAD)*4 + kk*32);
                MMA_F16(acc[2*ntp],   a[0],a[1],a[2],a[3], b[0],b[1]);
                MMA_F16(acc[2*ntp+1], a[0],a[1],a[2],a[3], b[2],b[3]);
            }
        }
        __syncthreads();
    }
    #pragma unroll
    for (int half = 0; half < 2; half++){
        int px = warp*16 + gid + half*8;
        float* pp = g_pred + (size_t)(b_*HW + p0 + px)*NOFF;
        #pragma unroll
        for (int nt = 0; nt < 4; nt++){
            int c = nt*8 + 2*tig;
            float v0 = acc[nt][half*2 + 0] + sB[c];
            float v1 = acc[nt][half*2 + 1] + sB[c+1];
            if (c >= 18)   v0 = 1.f/(1.f + __expf(-v0));
            if (c+1 >= 18) v1 = 1.f/(1.f + __expf(-v1));
            if (c < NOFF)   pp[c]   = v0;
            if (c+1 < NOFF) pp[c+1] = v1;
        }
    }
}

// ---------------- K3: deform conv via fp16 mma, K-chunk 64, double-buffered ----------------
#define K3_F_AS0  0
#define K3_F_AS1  (128*HPAD)
#define K3_F_BS0  (2*128*HPAD)
#define K3_F_BS1  (3*128*HPAD)
#define K3_F_IDX  (4*128*HPAD)
#define K3_F_WT   (K3_F_IDX + 4608)
#define K3_F_S    (K3_F_WT + 4608)
#define K3_F_T    (K3_F_S + 128)
#define K3_SMEM_F (K3_F_T + 128)

__global__ void __launch_bounds__(256, 2) k3_deform_mma(const float* __restrict__ dcnb,
        const float* __restrict__ g2, const float* __restrict__ b2,
        const float* __restrict__ m2, const float* __restrict__ v2){
    extern __shared__ float sm[];
    uint32_t* AsB[2] = { (uint32_t*)(sm + K3_F_AS0), (uint32_t*)(sm + K3_F_AS1) };
    int4*   sIdx = (int4*)(sm + K3_F_IDX);
    float4* sWt  = (float4*)(sm + K3_F_WT);
    float* sS = sm + K3_F_S;
    float* sT = sm + K3_F_T;

    int blk = blockIdx.x;
    int b_ = blk / 50;
    int p0 = (blk % 50) * 128;
    int tid = threadIdx.x, warp = tid >> 5, lane = tid & 31;

    // setup: precompute bilinear corner indices + mask/validity-folded weights
    for (int pr = tid; pr < 128*9; pr += 256){
        int p = pr / 9, nn = pr % 9;
        int pg = p0 + p, h = pg / Ww, w = pg % Ww;
        size_t pb = (size_t)(b_*HW + pg) * NOFF;
        float py = (float)(h - 1 + nn/3) + g_pred[pb + 2*nn];
        float qx = (float)(w - 1 + nn%3) + g_pred[pb + 2*nn + 1];
        float mk = g_pred[pb + 18 + nn];
        float y0f = floorf(py), x0f = floorf(qx);
        float wy = py - y0f, wx = qx - x0f;
        int iy0 = (int)y0f, ix0 = (int)x0f, iy1 = iy0 + 1, ix1 = ix0 + 1;
        float vy0 = (iy0 >= 0 && iy0 < Hh) ? 1.f : 0.f;
        float vy1 = (iy1 >= 0 && iy1 < Hh) ? 1.f : 0.f;
        float vx0 = (ix0 >= 0 && ix0 < Ww) ? 1.f : 0.f;
        float vx1 = (ix1 >= 0 && ix1 < Ww) ? 1.f : 0.f;
        int cy0 = min(max(iy0,0),Hh-1), cy1 = min(max(iy1,0),Hh-1);
        int cx0 = min(max(ix0,0),Ww-1), cx1 = min(max(ix1,0),Ww-1);
        int base = b_*HW;
        int4 id;
        id.x = (base + cy0*Ww + cx0)*CM;
        id.y = (base + cy0*Ww + cx1)*CM;
        id.z = (base + cy1*Ww + cx0)*CM;
        id.w = (base + cy1*Ww + cx1)*CM;
        float4 wt;
        wt.x = (1.f-wy)*(1.f-wx)*mk*vy0*vx0;
        wt.y = (1.f-wy)*wx      *mk*vy0*vx1;
        wt.z = wy*(1.f-wx)      *mk*vy1*vx0;
        wt.w = wy*wx            *mk*vy1*vx1;
        sIdx[pr] = id;
        sWt[pr]  = wt;
    }
    if (tid < 128){
        float s = g2[tid] * rsqrtf(v2[tid] + EPSF);
        sS[tid] = s;
        sT[tid] = dcnb[tid]*s + b2[tid] - m2[tid]*s;
    }
    __syncthreads();

    int wm = warp & 3, wnn = warp >> 2, gid = lane >> 2, tig = lane & 3;
    int sub = lane >> 3, grp = lane & 7;   // 4 px x 8 channel-groups (8ch each)
    float acc[2][8][4] = {};
    uint32_t asuB[2] = { s2u(AsB[0]), s2u(AsB[1]) };
    uint32_t bsuB[2] = { s2u((uint32_t*)(sm + K3_F_BS0)), s2u((uint32_t*)(sm + K3_F_BS1)) };

    auto fillB = [&](int it, int buf){
        int n = it >> 1, c0 = (it & 1) << 6;
        const __half* wn = g_wdh + (size_t)n*(CM*CM) + c0;
        uint32_t bu = bsuB[buf];
        #pragma unroll
        for (int i = 0; i < 4; i++){
            int u = i*256 + tid; int o = u >> 3, seg = u & 7;
            cpa16(bu + (o*HPAD + seg*4)*4, wn + o*CM + seg*8);
        }
    };
    auto fillA = [&](int it, int buf){
        int n = it >> 1, c0 = (it & 1) << 6;
        const __half* yb = g_yh + c0 + grp*8;
        uint32_t* Ad = AsB[buf];
        #pragma unroll
        for (int p = 0; p < 4; p++){
            int px = warp*16 + p*4 + sub;
            int pr = px*9 + n;
            int4   id = sIdx[pr];
            float4 wt = sWt[pr];
            uint4 c00 = *(const uint4*)(yb + id.x);
            uint4 c01 = *(const uint4*)(yb + id.y);
            uint4 c10 = *(const uint4*)(yb + id.z);
            uint4 c11 = *(const uint4*)(yb + id.w);
            uint4 t;
            #pragma unroll
            for (int q = 0; q < 4; q++){
                float2 f0 = __half22float2(((__half2*)&c00)[q]);
                float2 f1 = __half22float2(((__half2*)&c01)[q]);
                float2 f2 = __half22float2(((__half2*)&c10)[q]);
                float2 f3 = __half22float2(((__half2*)&c11)[q]);
                float2 v;
                v.x = wt.x*f0.x + wt.y*f1.x + wt.z*f2.x + wt.w*f3.x;
                v.y = wt.x*f0.y + wt.y*f1.y + wt.z*f2.y + wt.w*f3.y;
                ((__half2*)&t)[q] = __float22half2_rn(v);
            }
            *(uint4*)(Ad + px*HPAD + grp*4) = t;
        }
    };

    // prologue
    fillB(0, 0); CPA_COMMIT();
    fillA(0, 0);
    CPA_WAIT0();
    __syncthreads();

    int cur = 0;
    for (int it = 0; it < 18; it++){
        int nb = cur ^ 1;
        if (it < 17){ fillB(it+1, nb); CPA_COMMIT(); }
        mma_f16_128_k64(asuB[cur], bsuB[cur], wm, wnn, lane, acc);
        if (it < 17) fillA(it+1, nb);
        CPA_WAIT0();
        __syncthreads();
        cur = nb;
    }

    // epilogue: bn2 + silu -> g_zh (fp16 NHWC)
    #pragma unroll
    for (int mt = 0; mt < 2; mt++){
        int r0 = wm*32 + mt*16 + gid;
        __half2* z0 = (__half2*)(g_zh + (size_t)(b_*HW + p0 + r0)*CM);
        __half2* z1 = (__half2*)(g_zh + (size_t)(b_*HW + p0 + r0 + 8)*CM);
        #pragma unroll
        for (int nt = 0; nt < 8; nt++){
            int cb = wnn*64 + nt*8 + 2*tig;
            float s0 = sS[cb], s1 = sS[cb+1], t0 = sT[cb], t1 = sT[cb+1];
            z0[cb>>1] = __float22half2_rn(make_float2(
                silu_f(acc[mt][nt][0]*s0 + t0), silu_f(acc[mt][nt][1]*s1 + t1)));
            z1[cb>>1] = __float22half2_rn(make_float2(
                silu_f(acc[mt][nt][2]*s0 + t0), silu_f(acc[mt][nt][3]*s1 + t1)));
        }
    }
}

// ---------------- K4: conv1x1(128->256) + bn3 + silu + residual -> out (NCHW) ----------------
__global__ void __launch_bounds__(256, 2) k4_mma(const float* __restrict__ x, float* __restrict__ out,
        const float* __restrict__ g3, const float* __restrict__ b3,
        const float* __restrict__ m3, const float* __restrict__ v3){
    __shared__ __align__(16) uint32_t As[128*HPAD];
    __shared__ __align__(16) uint32_t Bs[128*HPAD];
    __shared__ float sS[128], sT[128];
    int blk = blockIdx.x;
    int b_ = blk / 50;
    int p0 = (blk % 50) * 128;
    int o0g = blockIdx.y * 128;
    int tid = threadIdx.x, warp = tid >> 5, lane = tid & 31;
    int wm = warp & 3, wnn = warp >> 2, gid = lane >> 2, tig = lane & 3;
    if (tid < 128){
        int o = o0g + tid;
        float s = g3[o] * rsqrtf(v3[o] + EPSF);
        sS[tid] = s;
        sT[tid] = b3[o] - m3[o]*s;
    }
    float acc[2][8][4] = {};
    const __half* zt = g_zh + (size_t)(b_*HW + p0)*CM;
    const __half* wb = g_w3h + (size_t)o0g*CM;
    uint32_t asu = s2u(As), bsu = s2u(Bs);
    for (int kc = 0; kc < 2; kc++){
        int k0 = kc*64;
        #pragma unroll
        for (int i = 0; i < 4; i++){
            int u = i*256 + tid; int r = u >> 3, seg = u & 7;
            cpa16(asu + (r*HPAD + seg*4)*4, zt + (size_t)r*CM + k0 + seg*8);
            cpa16(bsu + (r*HPAD + seg*4)*4, wb + r*CM + k0 + seg*8);
        }
        CPA_COMMIT();
        CPA_WAIT0();
        __syncthreads();
        mma_f16_128_k64(asu, bsu, wm, wnn, lane, acc);
        __syncthreads();
    }
    #pragma unroll
    for (int mt = 0; mt < 2; mt++){
        int pg0 = p0 + wm*32 + mt*16 + gid;
        #pragma unroll
        for (int nt = 0; nt < 8; nt++){
            int o = o0g + wnn*64 + nt*8 + 2*tig;
            float s0 = sS[o - o0g], s1 = sS[o - o0g + 1];
            float t0 = sT[o - o0g], t1 = sT[o - o0g + 1];
            size_t i00 = ((size_t)b_*C2 + o)*HW + pg0;
            size_t i01 = i00 + HW;
            out[i00]     = x[i00]     + silu_f(acc[mt][nt][0]*s0 + t0);
            out[i01]     = x[i01]     + silu_f(acc[mt][nt][1]*s1 + t1);
            out[i00 + 8] = x[i00 + 8] + silu_f(acc[mt][nt][2]*s0 + t0);
            out[i01 + 8] = x[i01 + 8] + silu_f(acc[mt][nt][3]*s1 + t1);
        }
    }
}

// ---------------- launch ----------------
extern "C" void kernel_launch(void* const* d_in, const int* in_sizes, int n_in,
                              void* d_out, int out_size){
    const float* x     = (const float*)d_in[0];
    const float* cv1_w = (const float*)d_in[1];
    const float* bn1g  = (const float*)d_in[2];
    const float* bn1b  = (const float*)d_in[3];
    const float* bn1m  = (const float*)d_in[4];
    const float* bn1v  = (const float*)d_in[5];
    const float* off_w = (const float*)d_in[6];
    const float* off_b = (const float*)d_in[7];
    const float* dcn_w = (const float*)d_in[8];
    const float* dcn_b = (const float*)d_in[9];
    const float* bn2g  = (const float*)d_in[10];
    const float* bn2b  = (const float*)d_in[11];
    const float* bn2m  = (const float*)d_in[12];
    const float* bn2v  = (const float*)d_in[13];
    const float* cv3_w = (const float*)d_in[14];
    const float* bn3g  = (const float*)d_in[15];
    const float* bn3b  = (const float*)d_in[16];
    const float* bn3m  = (const float*)d_in[17];
    const float* bn3v  = (const float*)d_in[18];
    float* out = (float*)d_out;

    prep_w<<<(N9*CM*CM + 255)/256, 256>>>(cv1_w, off_w, dcn_w, cv3_w);
    prep_xh<<<dim3(200, 8, 8), 256>>>(x);
    k1_mma<<<BSZ*50, 256>>>(bn1g, bn1b, bn1m, bn1v);
    k2_mma<<<BSZ*50, 256>>>(off_b);

    int smem_bytes = K3_SMEM_F * 4;  // 111616 B
    cudaFuncSetAttribute(k3_deform_mma, cudaFuncAttributeMaxDynamicSharedMemorySize, smem_bytes);
    k3_deform_mma<<<BSZ*50, 256, smem_bytes>>>(dcn_b, bn2g, bn2b, bn2m, bn2v);

    k4_mma<<<dim3(BSZ*50, 2), 256>>>(x, out, bn3g, bn3b, bn3m, bn3v);
}